// round 7
// baseline (speedup 1.0000x reference)
#include <cuda_runtime.h>
#include <cstdint>

// out[b,o] = concat(x, y, outer(x,y).flatten()) @ W[o,:]^T
// == GEMM C[1024,1024] = A[1024, 263168] * W^T, A generated on the fly:
//   k <  512          : A[b,k] = x[b,k]
//   512 <= k < 1024   : A[b,k] = y[b,k-512]
//   k >= 1024         : A[b,k] = x[b,(k-1024)>>9] * y[b,(k-1024)&511]
//
// 3xTF32 (A=Ah+Al, W=Wh+Wl, RNA bit-splits; C += Ah*Wh + Ah*Wl + Al*Wh) via
// mma.sync.aligned.m16n8k8.row.col.f32.tf32.tf32.f32.
//
// KEY FIX vs previous round: the tensor-core f32 accumulate rounds toward
// zero (RZ), giving a coherent ~-2e-3 bias over a 98,688-long accumulation
// chain. We bound the chain: every FLUSH=32 chunks the MMA accumulator is
// drained into a second fp32 register accumulator with ordinary RN adds,
// cutting the bias by ~sqrt(NCHUNK/FLUSH) and the chain-length factor.

namespace {

constexpr int kN1  = 512;
constexpr int kN2  = 512;
constexpr int kBS  = 1024;
constexpr int kOUT = 1024;
constexpr int kK   = kN1 + kN2 + kN1 * kN2;  // 263168

constexpr int BM = 64;
constexpr int BN = 64;
constexpr int KC = 16;
constexpr int LDSS = 20;               // padded smem row stride -> conflict-free frag reads
constexpr int NCHUNK = kK / KC;        // 16448
constexpr int FLUSH = 32;              // chunks per MMA-accumulator chain
constexpr int NBLK = NCHUNK / FLUSH;   // 514 (exact)

static_assert(NBLK * FLUSH == NCHUNK, "flush must divide chunk count");

// RNA truncation of fp32 to tf32 (19-bit): add half-ulp in bit space, mask.
__device__ __forceinline__ uint32_t tf32_rna_bits(float f) {
  uint32_t u = __float_as_uint(f);
  return (u + 0x1000u) & 0xFFFFE000u;
}

__device__ __forceinline__ void split_tf32(float v, uint32_t& hi, uint32_t& lo) {
  hi = tf32_rna_bits(v);
  float r = v - __uint_as_float(hi);   // exact (Sterbenz)
  lo = tf32_rna_bits(r);
}

__device__ __forceinline__ void mma_tf32(float c[4], const uint32_t a[4], const uint32_t b[2]) {
  asm volatile(
      "mma.sync.aligned.m16n8k8.row.col.f32.tf32.tf32.f32 "
      "{%0,%1,%2,%3}, {%4,%5,%6,%7}, {%8,%9}, {%0,%1,%2,%3};\n"
      : "+f"(c[0]), "+f"(c[1]), "+f"(c[2]), "+f"(c[3])
      : "r"(a[0]), "r"(a[1]), "r"(a[2]), "r"(a[3]), "r"(b[0]), "r"(b[1]));
}

__global__ __launch_bounds__(256, 2) void quad_bilinear_gemm(
    const float* __restrict__ x, const float* __restrict__ y,
    const float* __restrict__ W, float* __restrict__ out) {
  __shared__ __align__(16) uint32_t As_h[BM * LDSS];
  __shared__ __align__(16) uint32_t As_l[BM * LDSS];
  __shared__ __align__(16) uint32_t Ws_h[BN * LDSS];
  __shared__ __align__(16) uint32_t Ws_l[BN * LDSS];

  const int tid = threadIdx.x;
  const int b0 = blockIdx.x * BM;
  const int o0 = blockIdx.y * BN;

  // loader mapping: each thread owns one float4 (row, 4*k4) of both tiles
  const int row = tid >> 2;  // 0..63
  const int k4  = tid & 3;   // 0..3

  const float* __restrict__ xrow = x + (b0 + row) * kN1;
  const float* __restrict__ yrow = y + (b0 + row) * kN2;
  const float* __restrict__ wrow = W + (size_t)(o0 + row) * (size_t)kK + 4 * k4;

  // mma mapping: 8 warps = 2 (M) x 4 (N); warp tile 32x16 = 2x2 m16n8k8 tiles
  const int lane = tid & 31;
  const int warp = tid >> 5;
  const int wm = warp & 1;
  const int wn = warp >> 1;
  const int g = lane >> 2;  // groupID
  const int t = lane & 3;   // threadID in group

  float acc[2][2][4];  // short-chain MMA accumulator (RZ-accumulated by HW)
  float tot[2][2][4];  // long-run fp32 accumulator (RN FADD)
#pragma unroll
  for (int mi = 0; mi < 2; mi++)
#pragma unroll
    for (int ni = 0; ni < 2; ni++)
#pragma unroll
      for (int r = 0; r < 4; r++) { acc[mi][ni][r] = 0.f; tot[mi][ni][r] = 0.f; }

  // ---- prefetch chunk 0 (k0 = 0 -> x passthrough region for all lanes) ----
  float4 wv = *(const float4*)(wrow);
  float4 av = *(const float4*)(xrow + 4 * k4);
  float xs = 1.0f;

  for (int icb = 0; icb < NBLK; icb++) {
    for (int ic2 = 0; ic2 < FLUSH; ic2++) {
      const int ic = icb * FLUSH + ic2;

      // ---- split & store current chunk to smem ----
      {
        uint32_t h0, h1, h2, h3, l0, l1, l2, l3;
        split_tf32(xs * av.x, h0, l0);
        split_tf32(xs * av.y, h1, l1);
        split_tf32(xs * av.z, h2, l2);
        split_tf32(xs * av.w, h3, l3);
        *(uint4*)&As_h[row * LDSS + 4 * k4] = make_uint4(h0, h1, h2, h3);
        *(uint4*)&As_l[row * LDSS + 4 * k4] = make_uint4(l0, l1, l2, l3);

        split_tf32(wv.x, h0, l0);
        split_tf32(wv.y, h1, l1);
        split_tf32(wv.z, h2, l2);
        split_tf32(wv.w, h3, l3);
        *(uint4*)&Ws_h[row * LDSS + 4 * k4] = make_uint4(h0, h1, h2, h3);
        *(uint4*)&Ws_l[row * LDSS + 4 * k4] = make_uint4(l0, l1, l2, l3);
      }
      __syncthreads();

      // ---- prefetch next chunk (overlaps MMA phase) ----
      if (ic + 1 < NCHUNK) {
        const int k0n = (ic + 1) * KC;
        wv = *(const float4*)(wrow + k0n);
        const int k = k0n + 4 * k4;
        if (k < kN1) {
          av = *(const float4*)(xrow + k);
          xs = 1.0f;
        } else if (k < kN1 + kN2) {
          av = *(const float4*)(yrow + (k - kN1));
          xs = 1.0f;
        } else {
          const int kk = k - (kN1 + kN2);
          xs = xrow[kk >> 9];
          av = *(const float4*)(yrow + (kk & 511));
        }
      }

      // ---- MMA: 2 k-steps of 8, 3 split-products each ----
#pragma unroll
      for (int ks = 0; ks < 2; ks++) {
        uint32_t ah[2][4], al[2][4], bh[2][2], bl[2][2];
        const int c0 = ks * 8 + t;
#pragma unroll
        for (int mi = 0; mi < 2; mi++) {
          const int m0 = wm * 32 + mi * 16;
          ah[mi][0] = As_h[(m0 + g) * LDSS + c0];
          ah[mi][1] = As_h[(m0 + g + 8) * LDSS + c0];
          ah[mi][2] = As_h[(m0 + g) * LDSS + c0 + 4];
          ah[mi][3] = As_h[(m0 + g + 8) * LDSS + c0 + 4];
          al[mi][0] = As_l[(m0 + g) * LDSS + c0];
          al[mi][1] = As_l[(m0 + g + 8) * LDSS + c0];
          al[mi][2] = As_l[(m0 + g) * LDSS + c0 + 4];
          al[mi][3] = As_l[(m0 + g + 8) * LDSS + c0 + 4];
        }
#pragma unroll
        for (int ni = 0; ni < 2; ni++) {
          const int n0 = wn * 16 + ni * 8 + g;
          bh[ni][0] = Ws_h[n0 * LDSS + c0];
          bh[ni][1] = Ws_h[n0 * LDSS + c0 + 4];
          bl[ni][0] = Ws_l[n0 * LDSS + c0];
          bl[ni][1] = Ws_l[n0 * LDSS + c0 + 4];
        }
#pragma unroll
        for (int mi = 0; mi < 2; mi++)
#pragma unroll
          for (int ni = 0; ni < 2; ni++) {
            mma_tf32(acc[mi][ni], ah[mi], bh[ni]);  // hi*hi
            mma_tf32(acc[mi][ni], ah[mi], bl[ni]);  // hi*lo
            mma_tf32(acc[mi][ni], al[mi], bh[ni]);  // lo*hi
          }
      }
      __syncthreads();
    }

    // ---- flush: drain RZ-biased MMA chain into RN fp32 accumulator ----
#pragma unroll
    for (int mi = 0; mi < 2; mi++)
#pragma unroll
      for (int ni = 0; ni < 2; ni++)
#pragma unroll
        for (int r = 0; r < 4; r++) {
          tot[mi][ni][r] += acc[mi][ni][r];
          acc[mi][ni][r] = 0.f;
        }
  }

  // ---- epilogue: fragment -> gmem, each element written exactly once ----
#pragma unroll
  for (int mi = 0; mi < 2; mi++)
#pragma unroll
    for (int ni = 0; ni < 2; ni++) {
      const int r0 = b0 + wm * 32 + mi * 16 + g;
      const int c0 = o0 + wn * 16 + ni * 8 + 2 * t;
      *(float2*)(out + (size_t)r0 * kOUT + c0) =
          make_float2(tot[mi][ni][0], tot[mi][ni][1]);
      *(float2*)(out + (size_t)(r0 + 8) * kOUT + c0) =
          make_float2(tot[mi][ni][2], tot[mi][ni][3]);
    }
}

}  // namespace

extern "C" void kernel_launch(void* const* d_in, const int* in_sizes, int n_in,
                              void* d_out, int out_size) {
  (void)in_sizes; (void)n_in; (void)out_size;
  const float* x = (const float*)d_in[0];
  const float* y = (const float*)d_in[1];
  const float* W = (const float*)d_in[2];
  float* out = (float*)d_out;

  dim3 grid(kBS / BM, kOUT / BN);  // 16 x 16 = 256 CTAs
  quad_bilinear_gemm<<<grid, 256>>>(x, y, W, out);
}

// round 9
// speedup vs baseline: 2.1633x; 2.1633x over previous
#include <cuda_runtime.h>
#include <cstdint>

// C[1024,1024] = A[1024,263168] * W^T, A generated on the fly:
//  k<512: x | 512..1023: y | else A[b,k] = x[b,(k-1024)>>9] * y[b,(k-1024)&511]
//
// 3xBF16 split (RN hi; C += Ah*Wh + Ah*Wl + Al*Wh) on the legacy tensor path
// via mma.sync.aligned.m16n8k16.row.col.f32.bf16.bf16.f32 + ldmatrix.x4.
// RZ accumulator chains bounded to 48 adds (8-chunk windows), drained into
// RN fp32 register totals (mechanism validated in earlier rounds).

namespace {

constexpr int    kN1  = 512;
constexpr int    kOUT = 1024;
constexpr size_t kK   = 263168;

constexpr int BM = 128, BN = 64, KC = 32;
constexpr int NCHUNK = (int)(kK / KC);   // 8224
constexpr int WIN = 8;                   // 1028 windows exactly

constexpr int LDA  = 80;                 // smem row stride (bytes): conflict-free ldmatrix
constexpr int SZ_A = 128 * LDA;          // 10240 B per A tile (hi or lo)
constexpr int SZ_W = 64 * LDA;           //  5120 B per W tile

__device__ __forceinline__ uint32_t smem_u32(const void* p) {
  uint32_t a;
  asm("{ .reg .u64 t; cvta.to.shared.u64 t, %1; cvt.u32.u64 %0, t; }"
      : "=r"(a) : "l"(p));
  return a;
}

__device__ __forceinline__ void ldx4(uint32_t r[4], uint32_t addr) {
  asm volatile(
      "ldmatrix.sync.aligned.m8n8.x4.shared.b16 {%0,%1,%2,%3}, [%4];"
      : "=r"(r[0]), "=r"(r[1]), "=r"(r[2]), "=r"(r[3]) : "r"(addr));
}

__device__ __forceinline__ void mma16(float c[4], const uint32_t a[4],
                                      uint32_t b0, uint32_t b1) {
  asm volatile(
      "mma.sync.aligned.m16n8k16.row.col.f32.bf16.bf16.f32 "
      "{%0,%1,%2,%3}, {%4,%5,%6,%7}, {%8,%9}, {%0,%1,%2,%3};"
      : "+f"(c[0]), "+f"(c[1]), "+f"(c[2]), "+f"(c[3])
      : "r"(a[0]), "r"(a[1]), "r"(a[2]), "r"(a[3]), "r"(b0), "r"(b1));
}

__device__ __forceinline__ void sts128(uint32_t a, uint32_t v0, uint32_t v1,
                                       uint32_t v2, uint32_t v3) {
  asm volatile("st.shared.v4.b32 [%0], {%1,%2,%3,%4};"
               :: "r"(a), "r"(v0), "r"(v1), "r"(v2), "r"(v3) : "memory");
}

// (v0 = even k, v1 = odd k): h = {bf16(v1)|bf16(v0)} RN; l = residuals, RN.
__device__ __forceinline__ void split2(float v0, float v1, uint32_t& h, uint32_t& l) {
  asm("cvt.rn.bf16x2.f32 %0, %1, %2;" : "=r"(h) : "f"(v1), "f"(v0));
  float r0 = v0 - __uint_as_float(h << 16);
  float r1 = v1 - __uint_as_float(h & 0xFFFF0000u);
  asm("cvt.rn.bf16x2.f32 %0, %1, %2;" : "=r"(l) : "f"(r1), "f"(r0));
}

__global__ void __launch_bounds__(256, 1)
quad_hmma(const float* __restrict__ x, const float* __restrict__ y,
          const float* __restrict__ W, float* __restrict__ out) {
  __shared__ __align__(16) uint8_t sm[2 * SZ_A + 2 * SZ_W];  // 30720 B
  const uint32_t sAh = smem_u32(sm);
  const uint32_t sAl = sAh + SZ_A;
  const uint32_t sWh = sAl + SZ_A;
  const uint32_t sWl = sWh + SZ_W;

  const int tid = threadIdx.x, lane = tid & 31, warp = tid >> 5;
  const int wm = warp & 3, wn = warp >> 2;  // 4 m-warps x 2 n-warps
  const int b0 = blockIdx.x * BM, o0 = blockIdx.y * BN;

  // ---- producer mapping ----
  const int arow = tid >> 1, ahh = tid & 1;         // A: row, 16-elem k-half
  const float* __restrict__ xrow = x + (size_t)(b0 + arow) * kN1;
  const float* __restrict__ yrow = y + (size_t)(b0 + arow) * kN1;
  const int wrow = tid >> 2, wq = (tid & 3) * 8;    // W: row, 8-elem k-quarter
  const float* __restrict__ wsrc = W + (size_t)(o0 + wrow) * kK + wq;
  const uint32_t aSt = arow * LDA + ahh * 32;       // A STS byte offset
  const uint32_t wSt = wrow * LDA + wq * 2;         // W STS byte offset

  // ---- ldmatrix per-lane address offsets ----
  // A x4 mats: {m0-7,k0-7},{m8-15,k0-7},{m0-7,k8-15},{m8-15,k8-15} -> a0..a3
  const uint32_t aoff =
      (uint32_t)((wm * 32 + (lane & 7) + ((lane >> 3) & 1) * 8) * LDA +
                 (lane >> 4) * 16);
  // B x4 mats: {n0-7,k0-7},{n0-7,k8-15},{n8-15,k0-7},{n8-15,k8-15}
  const uint32_t boff =
      (uint32_t)(((lane & 7) + ((lane >> 4) & 1) * 8 + wn * 32) * LDA +
                 ((lane >> 3) & 1) * 16);

  const int g = lane >> 2, t = lane & 3;

  float acc[2][4][4], tot[2][4][4];
#pragma unroll
  for (int mt = 0; mt < 2; mt++)
#pragma unroll
    for (int nt = 0; nt < 4; nt++)
#pragma unroll
      for (int r = 0; r < 4; r++) { acc[mt][nt][r] = 0.f; tot[mt][nt][r] = 0.f; }

  // ---- prefetch chunk 0 (x passthrough region) ----
  float4 av[4];
  float4 wv0, wv1;
  float xs = 1.f;
  {
    const float* asrc = xrow + ahh * 16;
#pragma unroll
    for (int j = 0; j < 4; j++) av[j] = *(const float4*)(asrc + 4 * j);
    wv0 = *(const float4*)(wsrc);
    wv1 = *(const float4*)(wsrc + 4);
  }

  for (int ic = 0; ic < NCHUNK; ic++) {
    // ---- split & store current chunk ----
    {
      uint32_t h[8], l[8];
#pragma unroll
      for (int j = 0; j < 4; j++) {
        split2(av[j].x * xs, av[j].y * xs, h[2 * j], l[2 * j]);
        split2(av[j].z * xs, av[j].w * xs, h[2 * j + 1], l[2 * j + 1]);
      }
      sts128(sAh + aSt, h[0], h[1], h[2], h[3]);
      sts128(sAh + aSt + 16, h[4], h[5], h[6], h[7]);
      sts128(sAl + aSt, l[0], l[1], l[2], l[3]);
      sts128(sAl + aSt + 16, l[4], l[5], l[6], l[7]);

      uint32_t wh[4], wl[4];
      split2(wv0.x, wv0.y, wh[0], wl[0]);
      split2(wv0.z, wv0.w, wh[1], wl[1]);
      split2(wv1.x, wv1.y, wh[2], wl[2]);
      split2(wv1.z, wv1.w, wh[3], wl[3]);
      sts128(sWh + wSt, wh[0], wh[1], wh[2], wh[3]);
      sts128(sWl + wSt, wl[0], wl[1], wl[2], wl[3]);
    }
    __syncthreads();

    // ---- prefetch next chunk (overlaps MMA phase) ----
    if (ic + 1 < NCHUNK) {
      const int n = ic + 1;
      const float* asrc;
      if (n < 16) {
        asrc = xrow + n * 32 + ahh * 16;
        xs = 1.f;
      } else if (n < 32) {
        asrc = yrow + (n - 16) * 32 + ahh * 16;
        xs = 1.f;
      } else {
        const int t2 = n - 32;
        xs = xrow[t2 >> 4];
        asrc = yrow + (t2 & 15) * 32 + ahh * 16;
      }
#pragma unroll
      for (int j = 0; j < 4; j++) av[j] = *(const float4*)(asrc + 4 * j);
      const float* wp = wsrc + (size_t)n * KC;
      wv0 = *(const float4*)(wp);
      wv1 = *(const float4*)(wp + 4);
    }

    // ---- MMA phase: 2 ksteps x (8 ldmatrix.x4 + 24 HMMA) ----
#pragma unroll
    for (int ks = 0; ks < 2; ks++) {
      const uint32_t ko = ks * 32;
      uint32_t aH[2][4], aL[2][4], bH[2][4], bL[2][4];
#pragma unroll
      for (int mt = 0; mt < 2; mt++) {
        ldx4(aH[mt], sAh + aoff + mt * 16 * LDA + ko);
        ldx4(aL[mt], sAl + aoff + mt * 16 * LDA + ko);
      }
#pragma unroll
      for (int p = 0; p < 2; p++) {
        ldx4(bH[p], sWh + boff + p * 16 * LDA + ko);
        ldx4(bL[p], sWl + boff + p * 16 * LDA + ko);
      }
#pragma unroll
      for (int mt = 0; mt < 2; mt++)
#pragma unroll
        for (int nt = 0; nt < 4; nt++) {
          const int p = nt >> 1, o = (nt & 1) * 2;
          mma16(acc[mt][nt], aH[mt], bH[p][o], bH[p][o + 1]);  // hi*hi
          mma16(acc[mt][nt], aH[mt], bL[p][o], bL[p][o + 1]);  // hi*lo
          mma16(acc[mt][nt], aL[mt], bH[p][o], bH[p][o + 1]);  // lo*hi
        }
    }
    __syncthreads();

    // ---- window flush: bounded RZ chain -> RN fp32 totals ----
    if ((ic & (WIN - 1)) == WIN - 1) {
#pragma unroll
      for (int mt = 0; mt < 2; mt++)
#pragma unroll
        for (int nt = 0; nt < 4; nt++)
#pragma unroll
          for (int r = 0; r < 4; r++) {
            tot[mt][nt][r] += acc[mt][nt][r];
            acc[mt][nt][r] = 0.f;
          }
    }
  }

  // ---- epilogue: each element written exactly once ----
#pragma unroll
  for (int mt = 0; mt < 2; mt++)
#pragma unroll
    for (int nt = 0; nt < 4; nt++) {
      const int r0 = b0 + wm * 32 + mt * 16 + g;
      const int c0 = o0 + wn * 32 + nt * 8 + 2 * t;
      *(float2*)(out + (size_t)r0 * kOUT + c0) =
          make_float2(tot[mt][nt][0], tot[mt][nt][1]);
      *(float2*)(out + (size_t)(r0 + 8) * kOUT + c0) =
          make_float2(tot[mt][nt][2], tot[mt][nt][3]);
    }
}

}  // namespace

extern "C" void kernel_launch(void* const* d_in, const int* in_sizes, int n_in,
                              void* d_out, int out_size) {
  (void)in_sizes; (void)n_in; (void)out_size;
  const float* x = (const float*)d_in[0];
  const float* y = (const float*)d_in[1];
  const float* W = (const float*)d_in[2];
  float* out = (float*)d_out;

  dim3 grid(1024 / BM, kOUT / BN);  // 8 x 16 = 128 CTAs; same-W CTAs adjacent
  quad_hmma<<<grid, 256>>>(x, y, W, out);
}

// round 10
// speedup vs baseline: 2.4743x; 1.1438x over previous
#include <cuda_runtime.h>
#include <cuda_fp16.h>
#include <cstdint>

// C[1024,1024] = A[1024,263168] * W^T, A generated on the fly:
//  k<512: x | 512..1023: y | else A[b,k] = x[b,(k-1024)>>9] * y[b,(k-1024)&511]
//
// 2xFP16 scheme on the legacy tensor path (tcgen05 unavailable: harness PTX
// targets sm_103 without 'a'):  C ~= Ah*Wh + Ah*Wl, with Ah = rn_fp16(A),
// W = Wh + Wl (rn fp16 split). Dropped A-residual term => ~2.5e-4 rel err
// (threshold 1e-3). mma.m16n8k16.f16 + ldmatrix.x4, warp tile 64x32,
// CTA tile 128x128, split-K=2 (atomicAdd epilogue; exactly 2 commutative
// fp32 adds per element => deterministic). RZ accumulator chains bounded
// to 64 adds (WIN=16 chunks), drained into RN fp32 register totals.

namespace {

constexpr int    kN1  = 512;
constexpr int    kOUT = 1024;
constexpr size_t kK   = 263168;

constexpr int BM = 128, BN = 128, KC = 32;
constexpr int NHALF = 4112;              // chunks per K-half (2*4112*32 = 263168)
constexpr int WIN = 16;                  // 257 windows exactly

constexpr int LDA  = 80;                 // smem row stride (bytes), conflict-free ldmatrix
constexpr int SZ_A = 128 * LDA;          // A hi tile
constexpr int SZ_W = 128 * LDA;          // W hi / lo tiles

__device__ __forceinline__ uint32_t smem_u32(const void* p) {
  uint32_t a;
  asm("{ .reg .u64 t; cvta.to.shared.u64 t, %1; cvt.u32.u64 %0, t; }"
      : "=r"(a) : "l"(p));
  return a;
}

__device__ __forceinline__ void ldx4(uint32_t r[4], uint32_t addr) {
  asm volatile(
      "ldmatrix.sync.aligned.m8n8.x4.shared.b16 {%0,%1,%2,%3}, [%4];"
      : "=r"(r[0]), "=r"(r[1]), "=r"(r[2]), "=r"(r[3]) : "r"(addr));
}

__device__ __forceinline__ void mma16(float c[4], const uint32_t a[4],
                                      uint32_t b0, uint32_t b1) {
  asm volatile(
      "mma.sync.aligned.m16n8k16.row.col.f32.f16.f16.f32 "
      "{%0,%1,%2,%3}, {%4,%5,%6,%7}, {%8,%9}, {%0,%1,%2,%3};"
      : "+f"(c[0]), "+f"(c[1]), "+f"(c[2]), "+f"(c[3])
      : "r"(a[0]), "r"(a[1]), "r"(a[2]), "r"(a[3]), "r"(b0), "r"(b1));
}

__device__ __forceinline__ void sts128(uint32_t a, uint32_t v0, uint32_t v1,
                                       uint32_t v2, uint32_t v3) {
  asm volatile("st.shared.v4.b32 [%0], {%1,%2,%3,%4};"
               :: "r"(a), "r"(v0), "r"(v1), "r"(v2), "r"(v3) : "memory");
}

__device__ __forceinline__ uint32_t pack_h2(float v0, float v1) {
  __half2 h = __floats2half2_rn(v0, v1);
  return *reinterpret_cast<uint32_t*>(&h);
}
// hi = rn_fp16 pair; lo = rn_fp16 of residuals
__device__ __forceinline__ void split_h2(float v0, float v1, uint32_t& h,
                                         uint32_t& l) {
  __half2 hh = __floats2half2_rn(v0, v1);
  h = *reinterpret_cast<uint32_t*>(&hh);
  l = pack_h2(v0 - __low2float(hh), v1 - __high2float(hh));
}

__global__ void __launch_bounds__(256, 1)
quad_hmma2(const float* __restrict__ x, const float* __restrict__ y,
           const float* __restrict__ W, float* __restrict__ out) {
  __shared__ __align__(16) uint8_t sm[SZ_A + 2 * SZ_W];  // 30720 B
  const uint32_t sAh = smem_u32(sm);
  const uint32_t sWh = sAh + SZ_A;
  const uint32_t sWl = sWh + SZ_W;

  const int tid = threadIdx.x, lane = tid & 31, warp = tid >> 5;
  const int wm = warp >> 2, wn = warp & 3;  // 2 m-warps x 4 n-warps (64x32 tile)
  const int b0 = (blockIdx.x >> 1) * BM;
  const int half = blockIdx.x & 1;
  const int o0 = blockIdx.y * BN;
  const int gbase = half * NHALF;

  // ---- producer mapping: 2 threads per row, 16-elem k-half each ----
  const int prow = tid >> 1, phh = tid & 1;
  const float* __restrict__ xrow = x + (size_t)(b0 + prow) * kN1;
  const float* __restrict__ yrow = y + (size_t)(b0 + prow) * kN1;
  const float* __restrict__ wsrc = W + (size_t)(o0 + prow) * kK + phh * 16;
  const uint32_t pSt = prow * LDA + phh * 32;

  // ---- ldmatrix lane offsets ----
  const uint32_t aoff =
      (uint32_t)((wm * 64 + (lane & 7) + ((lane >> 3) & 1) * 8) * LDA +
                 (lane >> 4) * 16);
  const uint32_t boff =
      (uint32_t)((wn * 32 + (lane & 7) + ((lane >> 4) & 1) * 8) * LDA +
                 ((lane >> 3) & 1) * 16);
  const int g = lane >> 2, t = lane & 3;

  float acc[4][4][4], tot[4][4][4];
#pragma unroll
  for (int mt = 0; mt < 4; mt++)
#pragma unroll
    for (int nt = 0; nt < 4; nt++)
#pragma unroll
      for (int r = 0; r < 4; r++) { acc[mt][nt][r] = 0.f; tot[mt][nt][r] = 0.f; }

  // ---- prefetch + split chunk gbase ----
  uint32_t pAh[8], pWh[8], pWl[8];
  {
    const int gc = gbase;
    const float* asrc;
    float xs;
    if (gc < 16)      { asrc = xrow + gc * 32 + phh * 16;        xs = 1.f; }
    else if (gc < 32) { asrc = yrow + (gc - 16) * 32 + phh * 16; xs = 1.f; }
    else {
      const int t2 = gc - 32;
      xs = xrow[t2 >> 4];
      asrc = yrow + (t2 & 15) * 32 + phh * 16;
    }
#pragma unroll
    for (int j = 0; j < 4; j++) {
      float4 v = *(const float4*)(asrc + 4 * j);
      pAh[2 * j]     = pack_h2(v.x * xs, v.y * xs);
      pAh[2 * j + 1] = pack_h2(v.z * xs, v.w * xs);
    }
    const float* wp = wsrc + (size_t)gc * KC;
#pragma unroll
    for (int j = 0; j < 4; j++) {
      float4 v = *(const float4*)(wp + 4 * j);
      split_h2(v.x, v.y, pWh[2 * j], pWl[2 * j]);
      split_h2(v.z, v.w, pWh[2 * j + 1], pWl[2 * j + 1]);
    }
  }

  for (int ic = 0; ic < NHALF; ic++) {
    // ---- store pre-split chunk ----
    sts128(sAh + pSt, pAh[0], pAh[1], pAh[2], pAh[3]);
    sts128(sAh + pSt + 16, pAh[4], pAh[5], pAh[6], pAh[7]);
    sts128(sWh + pSt, pWh[0], pWh[1], pWh[2], pWh[3]);
    sts128(sWh + pSt + 16, pWh[4], pWh[5], pWh[6], pWh[7]);
    sts128(sWl + pSt, pWl[0], pWl[1], pWl[2], pWl[3]);
    sts128(sWl + pSt + 16, pWl[4], pWl[5], pWl[6], pWl[7]);
    __syncthreads();

    // ---- prefetch + split next chunk (overlaps MMA phase) ----
    if (ic + 1 < NHALF) {
      const int gc = gbase + ic + 1;
      const float* asrc;
      float xs;
      if (gc < 16)      { asrc = xrow + gc * 32 + phh * 16;        xs = 1.f; }
      else if (gc < 32) { asrc = yrow + (gc - 16) * 32 + phh * 16; xs = 1.f; }
      else {
        const int t2 = gc - 32;
        xs = xrow[t2 >> 4];
        asrc = yrow + (t2 & 15) * 32 + phh * 16;
      }
#pragma unroll
      for (int j = 0; j < 4; j++) {
        float4 v = *(const float4*)(asrc + 4 * j);
        pAh[2 * j]     = pack_h2(v.x * xs, v.y * xs);
        pAh[2 * j + 1] = pack_h2(v.z * xs, v.w * xs);
      }
      const float* wp = wsrc + (size_t)gc * KC;
#pragma unroll
      for (int j = 0; j < 4; j++) {
        float4 v = *(const float4*)(wp + 4 * j);
        split_h2(v.x, v.y, pWh[2 * j], pWl[2 * j]);
        split_h2(v.z, v.w, pWh[2 * j + 1], pWl[2 * j + 1]);
      }
    }

    // ---- MMA: 2 ksteps x (8 ldmatrix.x4 + 32 HMMA) ----
#pragma unroll
    for (int ks = 0; ks < 2; ks++) {
      const uint32_t ko = ks * 32;
      uint32_t aH[4][4], bH[2][4], bL[2][4];
#pragma unroll
      for (int mt = 0; mt < 4; mt++)
        ldx4(aH[mt], sAh + aoff + mt * (16 * LDA) + ko);
#pragma unroll
      for (int p = 0; p < 2; p++) {
        ldx4(bH[p], sWh + boff + p * (16 * LDA) + ko);
        ldx4(bL[p], sWl + boff + p * (16 * LDA) + ko);
      }
#pragma unroll
      for (int mt = 0; mt < 4; mt++)
#pragma unroll
        for (int nt = 0; nt < 4; nt++) {
          const int p = nt >> 1, o = (nt & 1) * 2;
          mma16(acc[mt][nt], aH[mt], bH[p][o], bH[p][o + 1]);  // Ah*Wh
          mma16(acc[mt][nt], aH[mt], bL[p][o], bL[p][o + 1]);  // Ah*Wl
        }
    }
    __syncthreads();

    // ---- bounded RZ chain -> RN fp32 totals ----
    if ((ic & (WIN - 1)) == WIN - 1) {
#pragma unroll
      for (int mt = 0; mt < 4; mt++)
#pragma unroll
        for (int nt = 0; nt < 4; nt++)
#pragma unroll
          for (int r = 0; r < 4; r++) {
            tot[mt][nt][r] += acc[mt][nt][r];
            acc[mt][nt][r] = 0.f;
          }
    }
  }

  // ---- epilogue: split-K combine; exactly 2 commutative fp32 adds/elem ----
#pragma unroll
  for (int mt = 0; mt < 4; mt++)
#pragma unroll
    for (int nt = 0; nt < 4; nt++) {
      const int r0 = b0 + wm * 64 + mt * 16 + g;
      const int c0 = o0 + wn * 32 + nt * 8 + 2 * t;
      atomicAdd(out + (size_t)r0 * kOUT + c0, tot[mt][nt][0]);
      atomicAdd(out + (size_t)r0 * kOUT + c0 + 1, tot[mt][nt][1]);
      atomicAdd(out + (size_t)(r0 + 8) * kOUT + c0, tot[mt][nt][2]);
      atomicAdd(out + (size_t)(r0 + 8) * kOUT + c0 + 1, tot[mt][nt][3]);
    }
}

}  // namespace

extern "C" void kernel_launch(void* const* d_in, const int* in_sizes, int n_in,
                              void* d_out, int out_size) {
  (void)in_sizes; (void)n_in; (void)out_size;
  const float* x = (const float*)d_in[0];
  const float* y = (const float*)d_in[1];
  const float* W = (const float*)d_in[2];
  float* out = (float*)d_out;

  cudaMemsetAsync(out, 0, (size_t)1024 * kOUT * sizeof(float));
  dim3 grid(16, 8);  // x: 8 b-tiles x 2 K-halves, y: 8 o-tiles -> 128 CTAs
  quad_hmma2<<<grid, 256>>>(x, y, W, out);
}

// round 11
// speedup vs baseline: 3.3202x; 1.3419x over previous
#include <cuda_runtime.h>
#include <cuda_fp16.h>
#include <cstdint>

// C[1024,1024] = A[1024,263168] * W^T, A generated on the fly:
//  k<512: x | 512..1023: y | else A[b,k] = x[b,(k-1024)>>9] * y[b,(k-1024)&511]
//
// 2xFP16 scheme (C ~= Ah*Wh + Ah*Wl), m16n8k16 HMMA + ldmatrix.x4,
// CTA tile 128x128, warp tile 64x32, split-K=2 with atomicAdd epilogue
// (exactly 2 commutative fp32 adds/element => deterministic).
// THIS ROUND: software pipeline with double-buffered smem stages so the
// producer (LDG/split/STS of chunk ic+1) overlaps the MMA phase of chunk ic;
// one __syncthreads per chunk. Arithmetic identical to the 7441us kernel
// (rel_err must reproduce 2.069e-4 exactly).

namespace {

constexpr int    kN1  = 512;
constexpr int    kOUT = 1024;
constexpr size_t kK   = 263168;

constexpr int BM = 128, BN = 128, KC = 32;
constexpr int NHALF = 4112;              // chunks per K-half
constexpr int WIN = 16;                  // 257 windows exactly

constexpr int LDA   = 80;                // smem row stride (bytes), conflict-free
constexpr int SZ_A  = 128 * LDA;
constexpr int SZ_W  = 128 * LDA;
constexpr int STAGE = SZ_A + 2 * SZ_W;   // 30720 B

__device__ __forceinline__ uint32_t smem_u32(const void* p) {
  uint32_t a;
  asm("{ .reg .u64 t; cvta.to.shared.u64 t, %1; cvt.u32.u64 %0, t; }"
      : "=r"(a) : "l"(p));
  return a;
}

__device__ __forceinline__ void ldx4(uint32_t r[4], uint32_t addr) {
  asm volatile(
      "ldmatrix.sync.aligned.m8n8.x4.shared.b16 {%0,%1,%2,%3}, [%4];"
      : "=r"(r[0]), "=r"(r[1]), "=r"(r[2]), "=r"(r[3]) : "r"(addr));
}

__device__ __forceinline__ void mma16(float c[4], const uint32_t a[4],
                                      uint32_t b0, uint32_t b1) {
  asm volatile(
      "mma.sync.aligned.m16n8k16.row.col.f32.f16.f16.f32 "
      "{%0,%1,%2,%3}, {%4,%5,%6,%7}, {%8,%9}, {%0,%1,%2,%3};"
      : "+f"(c[0]), "+f"(c[1]), "+f"(c[2]), "+f"(c[3])
      : "r"(a[0]), "r"(a[1]), "r"(a[2]), "r"(a[3]), "r"(b0), "r"(b1));
}

__device__ __forceinline__ void sts128(uint32_t a, uint32_t v0, uint32_t v1,
                                       uint32_t v2, uint32_t v3) {
  asm volatile("st.shared.v4.b32 [%0], {%1,%2,%3,%4};"
               :: "r"(a), "r"(v0), "r"(v1), "r"(v2), "r"(v3) : "memory");
}

__device__ __forceinline__ uint32_t pack_h2(float v0, float v1) {
  __half2 h = __floats2half2_rn(v0, v1);
  return *reinterpret_cast<uint32_t*>(&h);
}
__device__ __forceinline__ void split_h2(float v0, float v1, uint32_t& h,
                                         uint32_t& l) {
  __half2 hh = __floats2half2_rn(v0, v1);
  h = *reinterpret_cast<uint32_t*>(&hh);
  l = pack_h2(v0 - __low2float(hh), v1 - __high2float(hh));
}

__global__ void __launch_bounds__(256, 1)
quad_pipe(const float* __restrict__ x, const float* __restrict__ y,
          const float* __restrict__ W, float* __restrict__ out) {
  __shared__ __align__(16) uint8_t sm[2 * STAGE];  // 61440 B
  const uint32_t sb = smem_u32(sm);

  const int tid = threadIdx.x, lane = tid & 31, warp = tid >> 5;
  const int wm = warp >> 2, wn = warp & 3;  // 2 m-warps x 4 n-warps
  const int b0 = (blockIdx.x >> 1) * BM;
  const int half = blockIdx.x & 1;
  const int o0 = blockIdx.y * BN;
  const int gbase = half * NHALF;

  // ---- producer mapping: 2 threads per row, 16-elem k-half each ----
  const int prow = tid >> 1, phh = tid & 1;
  const float* __restrict__ xrow = x + (size_t)(b0 + prow) * kN1;
  const float* __restrict__ yrow = y + (size_t)(b0 + prow) * kN1;
  const float* __restrict__ wsrc = W + (size_t)(o0 + prow) * kK + phh * 16;
  const uint32_t pSt = prow * LDA + phh * 32;

  // ---- ldmatrix lane offsets ----
  const uint32_t aoff =
      (uint32_t)((wm * 64 + (lane & 7) + ((lane >> 3) & 1) * 8) * LDA +
                 (lane >> 4) * 16);
  const uint32_t boff =
      (uint32_t)((wn * 32 + (lane & 7) + ((lane >> 4) & 1) * 8) * LDA +
                 ((lane >> 3) & 1) * 16);
  const int g = lane >> 2, t = lane & 3;

  float acc[4][4][4], tot[4][4][4];
#pragma unroll
  for (int mt = 0; mt < 4; mt++)
#pragma unroll
    for (int nt = 0; nt < 4; nt++)
#pragma unroll
      for (int r = 0; r < 4; r++) { acc[mt][nt][r] = 0.f; tot[mt][nt][r] = 0.f; }

  // raw prefetch registers (chunk being produced)
  float4 av[4], wv[4];
  float xs;

  // ---- load + split + store chunk 0 into stage 0 ----
  {
    const int gc = gbase;
    const float* asrc;
    if (gc < 16)      { asrc = xrow + gc * 32 + phh * 16;        xs = 1.f; }
    else if (gc < 32) { asrc = yrow + (gc - 16) * 32 + phh * 16; xs = 1.f; }
    else {
      const int t2 = gc - 32;
      xs = xrow[t2 >> 4];
      asrc = yrow + (t2 & 15) * 32 + phh * 16;
    }
#pragma unroll
    for (int j = 0; j < 4; j++) av[j] = *(const float4*)(asrc + 4 * j);
    const float* wp = wsrc + (size_t)gc * KC;
#pragma unroll
    for (int j = 0; j < 4; j++) wv[j] = *(const float4*)(wp + 4 * j);

    uint32_t pA[8], pWh[8], pWl[8];
#pragma unroll
    for (int j = 0; j < 4; j++) {
      pA[2 * j]     = pack_h2(av[j].x * xs, av[j].y * xs);
      pA[2 * j + 1] = pack_h2(av[j].z * xs, av[j].w * xs);
      split_h2(wv[j].x, wv[j].y, pWh[2 * j], pWl[2 * j]);
      split_h2(wv[j].z, wv[j].w, pWh[2 * j + 1], pWl[2 * j + 1]);
    }
    const uint32_t s0 = sb;  // stage 0
    sts128(s0 + pSt, pA[0], pA[1], pA[2], pA[3]);
    sts128(s0 + pSt + 16, pA[4], pA[5], pA[6], pA[7]);
    sts128(s0 + SZ_A + pSt, pWh[0], pWh[1], pWh[2], pWh[3]);
    sts128(s0 + SZ_A + pSt + 16, pWh[4], pWh[5], pWh[6], pWh[7]);
    sts128(s0 + SZ_A + SZ_W + pSt, pWl[0], pWl[1], pWl[2], pWl[3]);
    sts128(s0 + SZ_A + SZ_W + pSt + 16, pWl[4], pWl[5], pWl[6], pWl[7]);
  }
  __syncthreads();

  for (int ic = 0; ic < NHALF; ic++) {
    const uint32_t rs = sb + (uint32_t)(ic & 1) * STAGE;        // read stage
    const uint32_t ws = sb + (uint32_t)((ic + 1) & 1) * STAGE;  // write stage
    const bool more = (ic + 1 < NHALF);

    // ---- issue raw LDGs for chunk ic+1 first (latency hides under MMA) ----
    if (more) {
      const int gc = gbase + ic + 1;
      const float* asrc;
      if (gc < 16)      { asrc = xrow + gc * 32 + phh * 16;        xs = 1.f; }
      else if (gc < 32) { asrc = yrow + (gc - 16) * 32 + phh * 16; xs = 1.f; }
      else {
        const int t2 = gc - 32;
        xs = xrow[t2 >> 4];
        asrc = yrow + (t2 & 15) * 32 + phh * 16;
      }
#pragma unroll
      for (int j = 0; j < 4; j++) av[j] = *(const float4*)(asrc + 4 * j);
      const float* wp = wsrc + (size_t)gc * KC;
#pragma unroll
      for (int j = 0; j < 4; j++) wv[j] = *(const float4*)(wp + 4 * j);
    }

    // ---- MMA phase on read stage: 2 ksteps x (8 ldmatrix.x4 + 32 HMMA) ----
#pragma unroll
    for (int ks = 0; ks < 2; ks++) {
      const uint32_t ko = ks * 32;
      uint32_t aH[4][4], bH[2][4], bL[2][4];
#pragma unroll
      for (int mt = 0; mt < 4; mt++)
        ldx4(aH[mt], rs + aoff + mt * (16 * LDA) + ko);
#pragma unroll
      for (int p = 0; p < 2; p++) {
        ldx4(bH[p], rs + SZ_A + boff + p * (16 * LDA) + ko);
        ldx4(bL[p], rs + SZ_A + SZ_W + boff + p * (16 * LDA) + ko);
      }
#pragma unroll
      for (int mt = 0; mt < 4; mt++)
#pragma unroll
        for (int nt = 0; nt < 4; nt++) {
          const int p = nt >> 1, o = (nt & 1) * 2;
          mma16(acc[mt][nt], aH[mt], bH[p][o], bH[p][o + 1]);  // Ah*Wh
          mma16(acc[mt][nt], aH[mt], bL[p][o], bL[p][o + 1]);  // Ah*Wl
        }
    }

    // ---- split + STS chunk ic+1 into write stage (overlaps MMA drain) ----
    if (more) {
      uint32_t pA[8], pWh[8], pWl[8];
#pragma unroll
      for (int j = 0; j < 4; j++) {
        pA[2 * j]     = pack_h2(av[j].x * xs, av[j].y * xs);
        pA[2 * j + 1] = pack_h2(av[j].z * xs, av[j].w * xs);
        split_h2(wv[j].x, wv[j].y, pWh[2 * j], pWl[2 * j]);
        split_h2(wv[j].z, wv[j].w, pWh[2 * j + 1], pWl[2 * j + 1]);
      }
      sts128(ws + pSt, pA[0], pA[1], pA[2], pA[3]);
      sts128(ws + pSt + 16, pA[4], pA[5], pA[6], pA[7]);
      sts128(ws + SZ_A + pSt, pWh[0], pWh[1], pWh[2], pWh[3]);
      sts128(ws + SZ_A + pSt + 16, pWh[4], pWh[5], pWh[6], pWh[7]);
      sts128(ws + SZ_A + SZ_W + pSt, pWl[0], pWl[1], pWl[2], pWl[3]);
      sts128(ws + SZ_A + SZ_W + pSt + 16, pWl[4], pWl[5], pWl[6], pWl[7]);
    }
    __syncthreads();

    // ---- bounded RZ chain -> RN fp32 totals ----
    if ((ic & (WIN - 1)) == WIN - 1) {
#pragma unroll
      for (int mt = 0; mt < 4; mt++)
#pragma unroll
        for (int nt = 0; nt < 4; nt++)
#pragma unroll
          for (int r = 0; r < 4; r++) {
            tot[mt][nt][r] += acc[mt][nt][r];
            acc[mt][nt][r] = 0.f;
          }
    }
  }

  // ---- epilogue: split-K combine; exactly 2 commutative fp32 adds/elem ----
#pragma unroll
  for (int mt = 0; mt < 4; mt++)
#pragma unroll
    for (int nt = 0; nt < 4; nt++) {
      const int r0 = b0 + wm * 64 + mt * 16 + g;
      const int c0 = o0 + wn * 32 + nt * 8 + 2 * t;
      atomicAdd(out + (size_t)r0 * kOUT + c0, tot[mt][nt][0]);
      atomicAdd(out + (size_t)r0 * kOUT + c0 + 1, tot[mt][nt][1]);
      atomicAdd(out + (size_t)(r0 + 8) * kOUT + c0, tot[mt][nt][2]);
      atomicAdd(out + (size_t)(r0 + 8) * kOUT + c0 + 1, tot[mt][nt][3]);
    }
}

}  // namespace

extern "C" void kernel_launch(void* const* d_in, const int* in_sizes, int n_in,
                              void* d_out, int out_size) {
  (void)in_sizes; (void)n_in; (void)out_size;
  const float* x = (const float*)d_in[0];
  const float* y = (const float*)d_in[1];
  const float* W = (const float*)d_in[2];
  float* out = (float*)d_out;

  cudaMemsetAsync(out, 0, (size_t)1024 * kOUT * sizeof(float));
  dim3 grid(16, 8);  // x: 8 b-tiles x 2 K-halves, y: 8 o-tiles -> 128 CTAs
  quad_pipe<<<grid, 256>>>(x, y, W, out);
}

// round 12
// speedup vs baseline: 4.8908x; 1.4730x over previous
#include <cuda_runtime.h>
#include <cuda_fp16.h>
#include <cstdint>

// out = concat(x, y, outer(x,y)) @ W^T, split into two kernels:
//  1) lin_pipe  : k < 1024 (x|y passthrough), proven R11 pipeline, 32 chunks,
//                 atomicAdd onto memset output.
//  2) quad_fact : bilinear part, FACTORIZED: out[b,o] += sum_i x[b,i]*(y[b,:]@W_i^T).
//     Y staged once as fp16 in smem; Y fragments register-held per 64-k j-block;
//     A-fragments regenerated per i via HMUL2 with fp16(x[b,i]) broadcast.
//     W streams through a double-buffered smem stage (the only per-chunk L1 user).
//     1xfp16 products, fp32 HMMA accum, RZ chains flushed to RN totals every
//     16 chunks (64-add chains, proven). Non-atomic += epilogue (one owner).

namespace {

constexpr int    kN1  = 512;
constexpr int    kOUT = 1024;
constexpr size_t kK   = 263168;

__device__ __forceinline__ uint32_t smem_u32(const void* p) {
  uint32_t a;
  asm("{ .reg .u64 t; cvta.to.shared.u64 t, %1; cvt.u32.u64 %0, t; }"
      : "=r"(a) : "l"(p));
  return a;
}
__device__ __forceinline__ void ldx4(uint32_t r[4], uint32_t addr) {
  asm volatile(
      "ldmatrix.sync.aligned.m8n8.x4.shared.b16 {%0,%1,%2,%3}, [%4];"
      : "=r"(r[0]), "=r"(r[1]), "=r"(r[2]), "=r"(r[3]) : "r"(addr));
}
__device__ __forceinline__ void mma16(float c[4], const uint32_t a[4],
                                      uint32_t b0, uint32_t b1) {
  asm volatile(
      "mma.sync.aligned.m16n8k16.row.col.f32.f16.f16.f32 "
      "{%0,%1,%2,%3}, {%4,%5,%6,%7}, {%8,%9}, {%0,%1,%2,%3};"
      : "+f"(c[0]), "+f"(c[1]), "+f"(c[2]), "+f"(c[3])
      : "r"(a[0]), "r"(a[1]), "r"(a[2]), "r"(a[3]), "r"(b0), "r"(b1));
}
__device__ __forceinline__ void sts128(uint32_t a, uint32_t v0, uint32_t v1,
                                       uint32_t v2, uint32_t v3) {
  asm volatile("st.shared.v4.b32 [%0], {%1,%2,%3,%4};"
               :: "r"(a), "r"(v0), "r"(v1), "r"(v2), "r"(v3) : "memory");
}
__device__ __forceinline__ void sts32(uint32_t a, float v) {
  asm volatile("st.shared.f32 [%0], %1;" :: "r"(a), "f"(v) : "memory");
}
__device__ __forceinline__ float lds32(uint32_t a) {
  float v;
  asm volatile("ld.shared.f32 %0, [%1];" : "=f"(v) : "r"(a));
  return v;
}
__device__ __forceinline__ uint32_t pack_h2(float v0, float v1) {
  __half2 h = __floats2half2_rn(v0, v1);
  return *reinterpret_cast<uint32_t*>(&h);
}
__device__ __forceinline__ void split_h2(float v0, float v1, uint32_t& h,
                                         uint32_t& l) {
  __half2 hh = __floats2half2_rn(v0, v1);
  h = *reinterpret_cast<uint32_t*>(&hh);
  l = pack_h2(v0 - __low2float(hh), v1 - __high2float(hh));
}
__device__ __forceinline__ uint32_t dup_h2(float f) {
  __half2 h = __half2half2(__float2half_rn(f));
  return *reinterpret_cast<uint32_t*>(&h);
}
__device__ __forceinline__ uint32_t hmul2u(uint32_t a, uint32_t b) {
  __half2 r = __hmul2(*reinterpret_cast<__half2*>(&a),
                      *reinterpret_cast<__half2*>(&b));
  return *reinterpret_cast<uint32_t*>(&r);
}

// ======================= linear part: proven R11 pipeline, 32 chunks ========
constexpr int L_LDA = 80, L_SZA = 128 * L_LDA, L_SZW = 128 * L_LDA;
constexpr int L_STAGE = L_SZA + 2 * L_SZW;
constexpr int LNH = 16;  // chunks per half: covers k < 1024

__global__ void __launch_bounds__(256, 1)
lin_pipe(const float* __restrict__ x, const float* __restrict__ y,
         const float* __restrict__ W, float* __restrict__ out) {
  __shared__ __align__(16) uint8_t sm[2 * L_STAGE];
  const uint32_t sb = smem_u32(sm);

  const int tid = threadIdx.x, lane = tid & 31, warp = tid >> 5;
  const int wm = warp >> 2, wn = warp & 3;
  const int b0 = (blockIdx.x >> 1) * 128;
  const int half = blockIdx.x & 1;
  const int o0 = blockIdx.y * 128;
  const int gbase = half * LNH;

  const int prow = tid >> 1, phh = tid & 1;
  const float* __restrict__ xrow = x + (size_t)(b0 + prow) * kN1;
  const float* __restrict__ yrow = y + (size_t)(b0 + prow) * kN1;
  const float* __restrict__ wsrc = W + (size_t)(o0 + prow) * kK + phh * 16;
  const uint32_t pSt = prow * L_LDA + phh * 32;

  const uint32_t aoff =
      (uint32_t)((wm * 64 + (lane & 7) + ((lane >> 3) & 1) * 8) * L_LDA +
                 (lane >> 4) * 16);
  const uint32_t boff =
      (uint32_t)((wn * 32 + (lane & 7) + ((lane >> 4) & 1) * 8) * L_LDA +
                 ((lane >> 3) & 1) * 16);
  const int g = lane >> 2, t = lane & 3;

  float acc[4][4][4];
#pragma unroll
  for (int mt = 0; mt < 4; mt++)
#pragma unroll
    for (int nt = 0; nt < 4; nt++)
#pragma unroll
      for (int r = 0; r < 4; r++) acc[mt][nt][r] = 0.f;

  float4 av[4], wv[4];
  float xs;

  {  // chunk 0 into stage 0
    const int gc = gbase;
    const float* asrc = (gc < 16) ? (xrow + gc * 32 + phh * 16)
                                  : (yrow + (gc - 16) * 32 + phh * 16);
    xs = 1.f;
#pragma unroll
    for (int j = 0; j < 4; j++) av[j] = *(const float4*)(asrc + 4 * j);
    const float* wp = wsrc + (size_t)gc * 32;
#pragma unroll
    for (int j = 0; j < 4; j++) wv[j] = *(const float4*)(wp + 4 * j);

    uint32_t pA[8], pWh[8], pWl[8];
#pragma unroll
    for (int j = 0; j < 4; j++) {
      pA[2 * j]     = pack_h2(av[j].x * xs, av[j].y * xs);
      pA[2 * j + 1] = pack_h2(av[j].z * xs, av[j].w * xs);
      split_h2(wv[j].x, wv[j].y, pWh[2 * j], pWl[2 * j]);
      split_h2(wv[j].z, wv[j].w, pWh[2 * j + 1], pWl[2 * j + 1]);
    }
    sts128(sb + pSt, pA[0], pA[1], pA[2], pA[3]);
    sts128(sb + pSt + 16, pA[4], pA[5], pA[6], pA[7]);
    sts128(sb + L_SZA + pSt, pWh[0], pWh[1], pWh[2], pWh[3]);
    sts128(sb + L_SZA + pSt + 16, pWh[4], pWh[5], pWh[6], pWh[7]);
    sts128(sb + L_SZA + L_SZW + pSt, pWl[0], pWl[1], pWl[2], pWl[3]);
    sts128(sb + L_SZA + L_SZW + pSt + 16, pWl[4], pWl[5], pWl[6], pWl[7]);
  }
  __syncthreads();

  for (int ic = 0; ic < LNH; ic++) {
    const uint32_t rs = sb + (uint32_t)(ic & 1) * L_STAGE;
    const uint32_t ws = sb + (uint32_t)((ic + 1) & 1) * L_STAGE;
    const bool more = (ic + 1 < LNH);

    if (more) {
      const int gc = gbase + ic + 1;
      const float* asrc = (gc < 16) ? (xrow + gc * 32 + phh * 16)
                                    : (yrow + (gc - 16) * 32 + phh * 16);
      xs = 1.f;
#pragma unroll
      for (int j = 0; j < 4; j++) av[j] = *(const float4*)(asrc + 4 * j);
      const float* wp = wsrc + (size_t)gc * 32;
#pragma unroll
      for (int j = 0; j < 4; j++) wv[j] = *(const float4*)(wp + 4 * j);
    }

#pragma unroll
    for (int ks = 0; ks < 2; ks++) {
      const uint32_t ko = ks * 32;
      uint32_t aH[4][4], bH[2][4], bL[2][4];
#pragma unroll
      for (int mt = 0; mt < 4; mt++)
        ldx4(aH[mt], rs + aoff + mt * (16 * L_LDA) + ko);
#pragma unroll
      for (int p = 0; p < 2; p++) {
        ldx4(bH[p], rs + L_SZA + boff + p * (16 * L_LDA) + ko);
        ldx4(bL[p], rs + L_SZA + L_SZW + boff + p * (16 * L_LDA) + ko);
      }
#pragma unroll
      for (int mt = 0; mt < 4; mt++)
#pragma unroll
        for (int nt = 0; nt < 4; nt++) {
          const int p = nt >> 1, o = (nt & 1) * 2;
          mma16(acc[mt][nt], aH[mt], bH[p][o], bH[p][o + 1]);
          mma16(acc[mt][nt], aH[mt], bL[p][o], bL[p][o + 1]);
        }
    }

    if (more) {
      uint32_t pA[8], pWh[8], pWl[8];
#pragma unroll
      for (int j = 0; j < 4; j++) {
        pA[2 * j]     = pack_h2(av[j].x * xs, av[j].y * xs);
        pA[2 * j + 1] = pack_h2(av[j].z * xs, av[j].w * xs);
        split_h2(wv[j].x, wv[j].y, pWh[2 * j], pWl[2 * j]);
        split_h2(wv[j].z, wv[j].w, pWh[2 * j + 1], pWl[2 * j + 1]);
      }
      sts128(ws + pSt, pA[0], pA[1], pA[2], pA[3]);
      sts128(ws + pSt + 16, pA[4], pA[5], pA[6], pA[7]);
      sts128(ws + L_SZA + pSt, pWh[0], pWh[1], pWh[2], pWh[3]);
      sts128(ws + L_SZA + pSt + 16, pWh[4], pWh[5], pWh[6], pWh[7]);
      sts128(ws + L_SZA + L_SZW + pSt, pWl[0], pWl[1], pWl[2], pWl[3]);
      sts128(ws + L_SZA + L_SZW + pSt + 16, pWl[4], pWl[5], pWl[6], pWl[7]);
    }
    __syncthreads();
  }

#pragma unroll
  for (int mt = 0; mt < 4; mt++)
#pragma unroll
    for (int nt = 0; nt < 4; nt++) {
      const int r0 = b0 + wm * 64 + mt * 16 + g;
      const int c0 = o0 + wn * 32 + nt * 8 + 2 * t;
      atomicAdd(out + (size_t)r0 * kOUT + c0, acc[mt][nt][0]);
      atomicAdd(out + (size_t)r0 * kOUT + c0 + 1, acc[mt][nt][1]);
      atomicAdd(out + (size_t)(r0 + 8) * kOUT + c0, acc[mt][nt][2]);
      atomicAdd(out + (size_t)(r0 + 8) * kOUT + c0 + 1, acc[mt][nt][3]);
    }
}

// ======================= bilinear part: factorized ==========================
constexpr int F_LDY  = 1040;                 // y_h row stride (bytes)
constexpr int F_YH   = 128 * F_LDY;          // 133120
constexpr int F_XS   = 64 * 512;             // 32768 (64 i x 128 rows x 4B)
constexpr int F_LDW  = 144;                  // W stage row stride (bytes)
constexpr int F_WST  = 64 * F_LDW;           // 9216
constexpr int F_SMEM = F_YH + F_XS + 2 * F_WST;  // 184320

__global__ void __launch_bounds__(256, 1)
quad_fact(const float* __restrict__ x, const float* __restrict__ y,
          const float* __restrict__ W, float* __restrict__ out) {
  extern __shared__ __align__(16) uint8_t dsm[];
  const uint32_t sY = smem_u32(dsm);
  const uint32_t sX = sY + F_YH;
  const uint32_t sW0 = sX + F_XS;

  const int tid = threadIdx.x, lane = tid & 31, warp = tid >> 5;
  const int wm = warp >> 2, wn = warp & 3;  // 2m x 4n, warp tile 64x16
  const int b0 = blockIdx.x * 128, o0 = blockIdx.y * 64;
  const int g = lane >> 2, t = lane & 3;

  // ---- stage Y as fp16 (once) ----
  {
    const int row = tid >> 1, h = tid & 1;
    const float* yr = y + (size_t)(b0 + row) * kN1 + h * 256;
    const uint32_t st = sY + row * F_LDY + h * 512;
#pragma unroll 4
    for (int c = 0; c < 256; c += 8) {
      float4 f0 = *(const float4*)(yr + c);
      float4 f1 = *(const float4*)(yr + c + 4);
      sts128(st + c * 2, pack_h2(f0.x, f0.y), pack_h2(f0.z, f0.w),
             pack_h2(f1.x, f1.y), pack_h2(f1.z, f1.w));
    }
  }

  // ---- W producer mapping: 4 threads per o-row, 16 k-floats each ----
  const int prow = tid >> 2, pq = (tid & 3) * 16;
  const float* __restrict__ wbase = W + (size_t)(o0 + prow) * kK + pq + 1024;
  const uint32_t wSt = prow * F_LDW + pq * 2;

  // ---- x-slab staging mapping ----
  const int xrow = tid >> 1, xih = tid & 1;
  const float* __restrict__ xbase = x + (size_t)(b0 + xrow) * kN1 + xih * 32;

  // ---- ldmatrix lane offsets (layouts proven in earlier rounds) ----
  const uint32_t aoff =
      (uint32_t)((wm * 64 + (lane & 7) + ((lane >> 3) & 1) * 8) * F_LDY +
                 (lane >> 4) * 16);
  const uint32_t boff =
      (uint32_t)((wn * 16 + (lane & 7) + ((lane >> 4) & 1) * 8) * F_LDW +
                 ((lane >> 3) & 1) * 16);

  float acc[4][2][4], tot[4][2][4];
#pragma unroll
  for (int mt = 0; mt < 4; mt++)
#pragma unroll
    for (int nt = 0; nt < 2; nt++)
#pragma unroll
      for (int r = 0; r < 4; r++) { acc[mt][nt][r] = 0.f; tot[mt][nt][r] = 0.f; }

  // ---- prologue: x-slab iblk 0 + W chunk 0 into stage 0 ----
  {
#pragma unroll
    for (int j = 0; j < 32; j += 4) {
      float4 v = *(const float4*)(xbase + j);
      const uint32_t a = sX + (xih * 32 + j) * 512 + xrow * 4;
      sts32(a, v.x); sts32(a + 512, v.y); sts32(a + 1024, v.z); sts32(a + 1536, v.w);
    }
    const float* wp = wbase;  // chunk 0: jb=0, i=0
    uint32_t h[8];
#pragma unroll
    for (int j = 0; j < 4; j++) {
      float4 v = *(const float4*)(wp + 4 * j);
      h[2 * j] = pack_h2(v.x, v.y);
      h[2 * j + 1] = pack_h2(v.z, v.w);
    }
    sts128(sW0 + wSt, h[0], h[1], h[2], h[3]);
    sts128(sW0 + wSt + 16, h[4], h[5], h[6], h[7]);
  }
  __syncthreads();

  uint32_t yf[4][4][4];  // [mt][ks][reg], register-held Y fragments for one jb

  for (int c = 0; c < 4096; c++) {
    const int jb = c >> 9, i = c & 511;

    if (i == 0) {  // new j-block: reload Y fragments (y_h is static)
#pragma unroll
      for (int mt = 0; mt < 4; mt++)
#pragma unroll
        for (int ks = 0; ks < 4; ks++)
          ldx4(yf[mt][ks], sY + aoff + jb * 128 + mt * (16 * F_LDY) + ks * 32);
    }
    if ((c & 63) == 0 && c) {  // new i-block: restage x-slab
      const int iblk = i >> 6;
#pragma unroll
      for (int j = 0; j < 32; j += 4) {
        float4 v = *(const float4*)(xbase + iblk * 64 + j);
        const uint32_t a = sX + (xih * 32 + j) * 512 + xrow * 4;
        sts32(a, v.x); sts32(a + 512, v.y); sts32(a + 1024, v.z); sts32(a + 1536, v.w);
      }
      __syncthreads();
    }

    const uint32_t rs = sW0 + (uint32_t)(c & 1) * F_WST;
    const uint32_t ws = sW0 + (uint32_t)((c + 1) & 1) * F_WST;
    const bool more = (c + 1 < 4096);

    // ---- LDG W chunk c+1 first (latency hides under MMA) ----
    float4 wv[4];
    if (more) {
      const int c2 = c + 1, j2 = c2 >> 9, i2 = c2 & 511;
      const float* wp = wbase + (size_t)i2 * 512 + j2 * 64;
#pragma unroll
      for (int j = 0; j < 4; j++) wv[j] = *(const float4*)(wp + 4 * j);
    }

    // ---- xs broadcasts for this i ----
    uint32_t xsd[4][2];
    {
      const uint32_t xb = sX + (uint32_t)(i & 63) * 512 + (wm * 64) * 4;
#pragma unroll
      for (int mt = 0; mt < 4; mt++) {
        xsd[mt][0] = dup_h2(lds32(xb + (mt * 16 + g) * 4));
        xsd[mt][1] = dup_h2(lds32(xb + (mt * 16 + g + 8) * 4));
      }
    }

    // ---- MMA: 4 ksteps x (1 W-ldx4 + 16 HMUL2 + 8 HMMA) ----
#pragma unroll
    for (int ks = 0; ks < 4; ks++) {
      uint32_t b[4];
      ldx4(b, rs + boff + ks * 32);
#pragma unroll
      for (int mt = 0; mt < 4; mt++) {
        uint32_t as[4];
        as[0] = hmul2u(yf[mt][ks][0], xsd[mt][0]);
        as[1] = hmul2u(yf[mt][ks][1], xsd[mt][1]);
        as[2] = hmul2u(yf[mt][ks][2], xsd[mt][0]);
        as[3] = hmul2u(yf[mt][ks][3], xsd[mt][1]);
        mma16(acc[mt][0], as, b[0], b[1]);
        mma16(acc[mt][1], as, b[2], b[3]);
      }
    }

    // ---- STS W chunk c+1 ----
    if (more) {
      uint32_t h[8];
#pragma unroll
      for (int j = 0; j < 4; j++) {
        h[2 * j] = pack_h2(wv[j].x, wv[j].y);
        h[2 * j + 1] = pack_h2(wv[j].z, wv[j].w);
      }
      sts128(ws + wSt, h[0], h[1], h[2], h[3]);
      sts128(ws + wSt + 16, h[4], h[5], h[6], h[7]);
    }
    __syncthreads();

    // ---- bounded RZ chain (64 adds) -> RN fp32 totals ----
    if ((c & 15) == 15) {
#pragma unroll
      for (int mt = 0; mt < 4; mt++)
#pragma unroll
        for (int nt = 0; nt < 2; nt++)
#pragma unroll
          for (int r = 0; r < 4; r++) {
            tot[mt][nt][r] += acc[mt][nt][r];
            acc[mt][nt][r] = 0.f;
          }
    }
  }

  // ---- epilogue: exclusive ownership, non-atomic += ----
#pragma unroll
  for (int mt = 0; mt < 4; mt++)
#pragma unroll
    for (int nt = 0; nt < 2; nt++) {
      const int r0 = b0 + wm * 64 + mt * 16 + g;
      const int c0 = o0 + wn * 16 + nt * 8 + 2 * t;
      out[(size_t)r0 * kOUT + c0]           += tot[mt][nt][0];
      out[(size_t)r0 * kOUT + c0 + 1]       += tot[mt][nt][1];
      out[(size_t)(r0 + 8) * kOUT + c0]     += tot[mt][nt][2];
      out[(size_t)(r0 + 8) * kOUT + c0 + 1] += tot[mt][nt][3];
    }
}

}  // namespace

extern "C" void kernel_launch(void* const* d_in, const int* in_sizes, int n_in,
                              void* d_out, int out_size) {
  (void)in_sizes; (void)n_in; (void)out_size;
  const float* x = (const float*)d_in[0];
  const float* y = (const float*)d_in[1];
  const float* W = (const float*)d_in[2];
  float* out = (float*)d_out;

  cudaFuncSetAttribute(quad_fact, cudaFuncAttributeMaxDynamicSharedMemorySize,
                       F_SMEM);

  cudaMemsetAsync(out, 0, (size_t)1024 * kOUT * sizeof(float));
  lin_pipe<<<dim3(16, 8), 256>>>(x, y, W, out);            // k < 1024
  quad_fact<<<dim3(8, 16), 256, F_SMEM>>>(x, y, W, out);   // bilinear part
}

// round 13
// speedup vs baseline: 5.4992x; 1.1244x over previous
#include <cuda_runtime.h>
#include <cuda_fp16.h>
#include <cstdint>

// out = concat(x, y, outer(x,y)) @ W^T, two kernels:
//  1) lin_pipe  : k < 1024 (x|y passthrough), proven pipeline, 32 chunks,
//                 atomicAdd onto memset output (exactly 2 commutative adds).
//  2) quad_fact : bilinear part FACTORIZED: out[b,o] += sum_i x[b,i]*(y@W_i^T).
//     Y staged once as fp16 in smem; Y fragments register-held per j-block;
//     A-fragments regenerated per i via HMUL2 with fp16(x[b,i]) broadcast;
//     W double-buffered. THIS ROUND: 512 threads / 16 warps (4m x 4n,
//     warp tile 32x16) instead of 256/8 -- identical arithmetic & chain
//     order (rel_err must reproduce 4.137952e-4), 2x warps per SMSP to
//     hide LDS/MMA latency exposed by ncu (tensor 24%, issue 18%, occ 12%).

namespace {

constexpr int    kN1  = 512;
constexpr int    kOUT = 1024;
constexpr size_t kK   = 263168;

__device__ __forceinline__ uint32_t smem_u32(const void* p) {
  uint32_t a;
  asm("{ .reg .u64 t; cvta.to.shared.u64 t, %1; cvt.u32.u64 %0, t; }"
      : "=r"(a) : "l"(p));
  return a;
}
__device__ __forceinline__ void ldx4(uint32_t r[4], uint32_t addr) {
  asm volatile(
      "ldmatrix.sync.aligned.m8n8.x4.shared.b16 {%0,%1,%2,%3}, [%4];"
      : "=r"(r[0]), "=r"(r[1]), "=r"(r[2]), "=r"(r[3]) : "r"(addr));
}
__device__ __forceinline__ void mma16(float c[4], const uint32_t a[4],
                                      uint32_t b0, uint32_t b1) {
  asm volatile(
      "mma.sync.aligned.m16n8k16.row.col.f32.f16.f16.f32 "
      "{%0,%1,%2,%3}, {%4,%5,%6,%7}, {%8,%9}, {%0,%1,%2,%3};"
      : "+f"(c[0]), "+f"(c[1]), "+f"(c[2]), "+f"(c[3])
      : "r"(a[0]), "r"(a[1]), "r"(a[2]), "r"(a[3]), "r"(b0), "r"(b1));
}
__device__ __forceinline__ void sts128(uint32_t a, uint32_t v0, uint32_t v1,
                                       uint32_t v2, uint32_t v3) {
  asm volatile("st.shared.v4.b32 [%0], {%1,%2,%3,%4};"
               :: "r"(a), "r"(v0), "r"(v1), "r"(v2), "r"(v3) : "memory");
}
__device__ __forceinline__ void sts32(uint32_t a, float v) {
  asm volatile("st.shared.f32 [%0], %1;" :: "r"(a), "f"(v) : "memory");
}
__device__ __forceinline__ float lds32(uint32_t a) {
  float v;
  asm volatile("ld.shared.f32 %0, [%1];" : "=f"(v) : "r"(a));
  return v;
}
__device__ __forceinline__ uint32_t pack_h2(float v0, float v1) {
  __half2 h = __floats2half2_rn(v0, v1);
  return *reinterpret_cast<uint32_t*>(&h);
}
__device__ __forceinline__ void split_h2(float v0, float v1, uint32_t& h,
                                         uint32_t& l) {
  __half2 hh = __floats2half2_rn(v0, v1);
  h = *reinterpret_cast<uint32_t*>(&hh);
  l = pack_h2(v0 - __low2float(hh), v1 - __high2float(hh));
}
__device__ __forceinline__ uint32_t dup_h2(float f) {
  __half2 h = __half2half2(__float2half_rn(f));
  return *reinterpret_cast<uint32_t*>(&h);
}
__device__ __forceinline__ uint32_t hmul2u(uint32_t a, uint32_t b) {
  __half2 r = __hmul2(*reinterpret_cast<__half2*>(&a),
                      *reinterpret_cast<__half2*>(&b));
  return *reinterpret_cast<uint32_t*>(&r);
}

// ======================= linear part (k<1024): proven pipeline ==============
constexpr int L_LDA = 80, L_SZA = 128 * L_LDA, L_SZW = 128 * L_LDA;
constexpr int L_STAGE = L_SZA + 2 * L_SZW;
constexpr int LNH = 16;

__global__ void __launch_bounds__(256, 1)
lin_pipe(const float* __restrict__ x, const float* __restrict__ y,
         const float* __restrict__ W, float* __restrict__ out) {
  __shared__ __align__(16) uint8_t sm[2 * L_STAGE];
  const uint32_t sb = smem_u32(sm);

  const int tid = threadIdx.x, lane = tid & 31, warp = tid >> 5;
  const int wm = warp >> 2, wn = warp & 3;
  const int b0 = (blockIdx.x >> 1) * 128;
  const int half = blockIdx.x & 1;
  const int o0 = blockIdx.y * 128;
  const int gbase = half * LNH;

  const int prow = tid >> 1, phh = tid & 1;
  const float* __restrict__ xrow = x + (size_t)(b0 + prow) * kN1;
  const float* __restrict__ yrow = y + (size_t)(b0 + prow) * kN1;
  const float* __restrict__ wsrc = W + (size_t)(o0 + prow) * kK + phh * 16;
  const uint32_t pSt = prow * L_LDA + phh * 32;

  const uint32_t aoff =
      (uint32_t)((wm * 64 + (lane & 15)) * L_LDA + (lane >> 4) * 16);
  const uint32_t boff =
      (uint32_t)((wn * 32 + (lane & 7) + ((lane >> 4) & 1) * 8) * L_LDA +
                 ((lane >> 3) & 1) * 16);
  const int g = lane >> 2, t = lane & 3;

  float acc[4][4][4];
#pragma unroll
  for (int mt = 0; mt < 4; mt++)
#pragma unroll
    for (int nt = 0; nt < 4; nt++)
#pragma unroll
      for (int r = 0; r < 4; r++) acc[mt][nt][r] = 0.f;

  float4 av[4], wv[4];

  {  // chunk 0 into stage 0
    const int gc = gbase;
    const float* asrc = (gc < 16) ? (xrow + gc * 32 + phh * 16)
                                  : (yrow + (gc - 16) * 32 + phh * 16);
#pragma unroll
    for (int j = 0; j < 4; j++) av[j] = *(const float4*)(asrc + 4 * j);
    const float* wp = wsrc + (size_t)gc * 32;
#pragma unroll
    for (int j = 0; j < 4; j++) wv[j] = *(const float4*)(wp + 4 * j);

    uint32_t pA[8], pWh[8], pWl[8];
#pragma unroll
    for (int j = 0; j < 4; j++) {
      pA[2 * j]     = pack_h2(av[j].x, av[j].y);
      pA[2 * j + 1] = pack_h2(av[j].z, av[j].w);
      split_h2(wv[j].x, wv[j].y, pWh[2 * j], pWl[2 * j]);
      split_h2(wv[j].z, wv[j].w, pWh[2 * j + 1], pWl[2 * j + 1]);
    }
    sts128(sb + pSt, pA[0], pA[1], pA[2], pA[3]);
    sts128(sb + pSt + 16, pA[4], pA[5], pA[6], pA[7]);
    sts128(sb + L_SZA + pSt, pWh[0], pWh[1], pWh[2], pWh[3]);
    sts128(sb + L_SZA + pSt + 16, pWh[4], pWh[5], pWh[6], pWh[7]);
    sts128(sb + L_SZA + L_SZW + pSt, pWl[0], pWl[1], pWl[2], pWl[3]);
    sts128(sb + L_SZA + L_SZW + pSt + 16, pWl[4], pWl[5], pWl[6], pWl[7]);
  }
  __syncthreads();

  for (int ic = 0; ic < LNH; ic++) {
    const uint32_t rs = sb + (uint32_t)(ic & 1) * L_STAGE;
    const uint32_t ws = sb + (uint32_t)((ic + 1) & 1) * L_STAGE;
    const bool more = (ic + 1 < LNH);

    if (more) {
      const int gc = gbase + ic + 1;
      const float* asrc = (gc < 16) ? (xrow + gc * 32 + phh * 16)
                                    : (yrow + (gc - 16) * 32 + phh * 16);
#pragma unroll
      for (int j = 0; j < 4; j++) av[j] = *(const float4*)(asrc + 4 * j);
      const float* wp = wsrc + (size_t)gc * 32;
#pragma unroll
      for (int j = 0; j < 4; j++) wv[j] = *(const float4*)(wp + 4 * j);
    }

#pragma unroll
    for (int ks = 0; ks < 2; ks++) {
      const uint32_t ko = ks * 32;
      uint32_t aH[4][4], bH[2][4], bL[2][4];
#pragma unroll
      for (int mt = 0; mt < 4; mt++)
        ldx4(aH[mt], rs + aoff + mt * (16 * L_LDA) + ko);
#pragma unroll
      for (int p = 0; p < 2; p++) {
        ldx4(bH[p], rs + L_SZA + boff + p * (16 * L_LDA) + ko);
        ldx4(bL[p], rs + L_SZA + L_SZW + boff + p * (16 * L_LDA) + ko);
      }
#pragma unroll
      for (int mt = 0; mt < 4; mt++)
#pragma unroll
        for (int nt = 0; nt < 4; nt++) {
          const int p = nt >> 1, o = (nt & 1) * 2;
          mma16(acc[mt][nt], aH[mt], bH[p][o], bH[p][o + 1]);
          mma16(acc[mt][nt], aH[mt], bL[p][o], bL[p][o + 1]);
        }
    }

    if (more) {
      uint32_t pA[8], pWh[8], pWl[8];
#pragma unroll
      for (int j = 0; j < 4; j++) {
        pA[2 * j]     = pack_h2(av[j].x, av[j].y);
        pA[2 * j + 1] = pack_h2(av[j].z, av[j].w);
        split_h2(wv[j].x, wv[j].y, pWh[2 * j], pWl[2 * j]);
        split_h2(wv[j].z, wv[j].w, pWh[2 * j + 1], pWl[2 * j + 1]);
      }
      sts128(ws + pSt, pA[0], pA[1], pA[2], pA[3]);
      sts128(ws + pSt + 16, pA[4], pA[5], pA[6], pA[7]);
      sts128(ws + L_SZA + pSt, pWh[0], pWh[1], pWh[2], pWh[3]);
      sts128(ws + L_SZA + pSt + 16, pWh[4], pWh[5], pWh[6], pWh[7]);
      sts128(ws + L_SZA + L_SZW + pSt, pWl[0], pWl[1], pWl[2], pWl[3]);
      sts128(ws + L_SZA + L_SZW + pSt + 16, pWl[4], pWl[5], pWl[6], pWl[7]);
    }
    __syncthreads();
  }

#pragma unroll
  for (int mt = 0; mt < 4; mt++)
#pragma unroll
    for (int nt = 0; nt < 4; nt++) {
      const int r0 = b0 + wm * 64 + mt * 16 + g;
      const int c0 = o0 + wn * 32 + nt * 8 + 2 * t;
      atomicAdd(out + (size_t)r0 * kOUT + c0, acc[mt][nt][0]);
      atomicAdd(out + (size_t)r0 * kOUT + c0 + 1, acc[mt][nt][1]);
      atomicAdd(out + (size_t)(r0 + 8) * kOUT + c0, acc[mt][nt][2]);
      atomicAdd(out + (size_t)(r0 + 8) * kOUT + c0 + 1, acc[mt][nt][3]);
    }
}

// ======================= bilinear part: factorized, 512 threads =============
constexpr int F_LDY  = 1040;
constexpr int F_YH   = 128 * F_LDY;              // 133120
constexpr int F_XS   = 64 * 512;                 // 32768
constexpr int F_LDW  = 144;
constexpr int F_WST  = 64 * F_LDW;               // 9216
constexpr int F_SMEM = F_YH + F_XS + 2 * F_WST;  // 184320

__global__ void __launch_bounds__(512, 1)
quad_fact(const float* __restrict__ x, const float* __restrict__ y,
          const float* __restrict__ W, float* __restrict__ out) {
  extern __shared__ __align__(16) uint8_t dsm[];
  const uint32_t sY = smem_u32(dsm);
  const uint32_t sX = sY + F_YH;
  const uint32_t sW0 = sX + F_XS;

  const int tid = threadIdx.x, lane = tid & 31, warp = tid >> 5;
  const int wm = warp & 3, wn = warp >> 2;  // 4m x 4n, warp tile 32x16
  const int b0 = blockIdx.x * 128, o0 = blockIdx.y * 64;
  const int g = lane >> 2, t = lane & 3;

  // ---- stage Y as fp16 (once): 512 threads, 128 cols each ----
  {
    const int row = tid >> 2, h = tid & 3;
    const float* yr = y + (size_t)(b0 + row) * kN1 + h * 128;
    const uint32_t st = sY + row * F_LDY + h * 256;
#pragma unroll 4
    for (int c = 0; c < 128; c += 8) {
      float4 f0 = *(const float4*)(yr + c);
      float4 f1 = *(const float4*)(yr + c + 4);
      sts128(st + c * 2, pack_h2(f0.x, f0.y), pack_h2(f0.z, f0.w),
             pack_h2(f1.x, f1.y), pack_h2(f1.z, f1.w));
    }
  }

  // ---- W producer: 8 threads per o-row, 8 k-floats each ----
  const int prow = tid >> 3, pq = (tid & 7) * 8;
  const float* __restrict__ wbase = W + (size_t)(o0 + prow) * kK + pq + 1024;
  const uint32_t wSt = prow * F_LDW + pq * 2;

  // ---- x-slab staging: 4 threads per row, 16 i each ----
  const int xrw = tid >> 2, xih = tid & 3;
  const float* __restrict__ xbase = x + (size_t)(b0 + xrw) * kN1 + xih * 16;

  // ---- ldmatrix lane offsets ----
  const uint32_t aoff =
      (uint32_t)((wm * 32 + (lane & 15)) * F_LDY + (lane >> 4) * 16);
  const uint32_t boff =
      (uint32_t)((wn * 16 + (lane & 7) + ((lane >> 4) & 1) * 8) * F_LDW +
                 ((lane >> 3) & 1) * 16);

  float acc[2][2][4], tot[2][2][4];
#pragma unroll
  for (int mt = 0; mt < 2; mt++)
#pragma unroll
    for (int nt = 0; nt < 2; nt++)
#pragma unroll
      for (int r = 0; r < 4; r++) { acc[mt][nt][r] = 0.f; tot[mt][nt][r] = 0.f; }

  // ---- prologue: x-slab iblk 0 + W chunk 0 into stage 0 ----
  {
#pragma unroll
    for (int j = 0; j < 16; j += 4) {
      float4 v = *(const float4*)(xbase + j);
      const uint32_t a = sX + (xih * 16 + j) * 512 + xrw * 4;
      sts32(a, v.x); sts32(a + 512, v.y); sts32(a + 1024, v.z); sts32(a + 1536, v.w);
    }
    float4 v0 = *(const float4*)(wbase);
    float4 v1 = *(const float4*)(wbase + 4);
    sts128(sW0 + wSt, pack_h2(v0.x, v0.y), pack_h2(v0.z, v0.w),
           pack_h2(v1.x, v1.y), pack_h2(v1.z, v1.w));
  }
  __syncthreads();

  uint32_t yf[2][4][4];  // [mt][ks][reg]

  for (int c = 0; c < 4096; c++) {
    const int jb = c >> 9, i = c & 511;

    if (i == 0) {  // new j-block: reload Y fragments (sY is static)
#pragma unroll
      for (int mt = 0; mt < 2; mt++)
#pragma unroll
        for (int ks = 0; ks < 4; ks++)
          ldx4(yf[mt][ks], sY + aoff + jb * 128 + mt * (16 * F_LDY) + ks * 32);
    }
    if ((c & 63) == 0 && c) {  // new i-block: restage x-slab
      const int iblk = i >> 6;
#pragma unroll
      for (int j = 0; j < 16; j += 4) {
        float4 v = *(const float4*)(xbase + iblk * 64 + j);
        const uint32_t a = sX + (xih * 16 + j) * 512 + xrw * 4;
        sts32(a, v.x); sts32(a + 512, v.y); sts32(a + 1024, v.z); sts32(a + 1536, v.w);
      }
      __syncthreads();
    }

    const uint32_t rs = sW0 + (uint32_t)(c & 1) * F_WST;
    const uint32_t ws = sW0 + (uint32_t)((c + 1) & 1) * F_WST;
    const bool more = (c + 1 < 4096);

    // ---- LDG W chunk c+1 first (latency hides under MMA) ----
    float4 wv0, wv1;
    if (more) {
      const int c2 = c + 1, j2 = c2 >> 9, i2 = c2 & 511;
      const float* wp = wbase + (size_t)i2 * 512 + j2 * 64;
      wv0 = *(const float4*)(wp);
      wv1 = *(const float4*)(wp + 4);
    }

    // ---- xs broadcasts for this i ----
    uint32_t xsd[2][2];
    {
      const uint32_t xb = sX + (uint32_t)(i & 63) * 512 + (wm * 32) * 4;
#pragma unroll
      for (int mt = 0; mt < 2; mt++) {
        xsd[mt][0] = dup_h2(lds32(xb + (mt * 16 + g) * 4));
        xsd[mt][1] = dup_h2(lds32(xb + (mt * 16 + g + 8) * 4));
      }
    }

    // ---- MMA: 4 ksteps x (1 W-ldx4 + 8 HMUL2 + 4 HMMA) ----
#pragma unroll
    for (int ks = 0; ks < 4; ks++) {
      uint32_t b[4];
      ldx4(b, rs + boff + ks * 32);
#pragma unroll
      for (int mt = 0; mt < 2; mt++) {
        uint32_t as[4];
        as[0] = hmul2u(yf[mt][ks][0], xsd[mt][0]);
        as[1] = hmul2u(yf[mt][ks][1], xsd[mt][1]);
        as[2] = hmul2u(yf[mt][ks][2], xsd[mt][0]);
        as[3] = hmul2u(yf[mt][ks][3], xsd[mt][1]);
        mma16(acc[mt][0], as, b[0], b[1]);
        mma16(acc[mt][1], as, b[2], b[3]);
      }
    }

    // ---- STS W chunk c+1 ----
    if (more) {
      sts128(ws + wSt, pack_h2(wv0.x, wv0.y), pack_h2(wv0.z, wv0.w),
             pack_h2(wv1.x, wv1.y), pack_h2(wv1.z, wv1.w));
    }
    __syncthreads();

    // ---- bounded RZ chain (64 adds) -> RN fp32 totals ----
    if ((c & 15) == 15) {
#pragma unroll
      for (int mt = 0; mt < 2; mt++)
#pragma unroll
        for (int nt = 0; nt < 2; nt++)
#pragma unroll
          for (int r = 0; r < 4; r++) {
            tot[mt][nt][r] += acc[mt][nt][r];
            acc[mt][nt][r] = 0.f;
          }
    }
  }

  // ---- epilogue: exclusive ownership, non-atomic += ----
#pragma unroll
  for (int mt = 0; mt < 2; mt++)
#pragma unroll
    for (int nt = 0; nt < 2; nt++) {
      const int r0 = b0 + wm * 32 + mt * 16 + g;
      const int c0 = o0 + wn * 16 + nt * 8 + 2 * t;
      out[(size_t)r0 * kOUT + c0]           += tot[mt][nt][0];
      out[(size_t)r0 * kOUT + c0 + 1]       += tot[mt][nt][1];
      out[(size_t)(r0 + 8) * kOUT + c0]     += tot[mt][nt][2];
      out[(size_t)(r0 + 8) * kOUT + c0 + 1] += tot[mt][nt][3];
    }
}

}  // namespace

extern "C" void kernel_launch(void* const* d_in, const int* in_sizes, int n_in,
                              void* d_out, int out_size) {
  (void)in_sizes; (void)n_in; (void)out_size;
  const float* x = (const float*)d_in[0];
  const float* y = (const float*)d_in[1];
  const float* W = (const float*)d_in[2];
  float* out = (float*)d_out;

  cudaFuncSetAttribute(quad_fact, cudaFuncAttributeMaxDynamicSharedMemorySize,
                       F_SMEM);

  cudaMemsetAsync(out, 0, (size_t)1024 * kOUT * sizeof(float));
  lin_pipe<<<dim3(16, 8), 256>>>(x, y, W, out);            // k < 1024
  quad_fact<<<dim3(8, 16), 512, F_SMEM>>>(x, y, W, out);   // bilinear part
}

// round 14
// speedup vs baseline: 7.3444x; 1.3355x over previous
#include <cuda_runtime.h>
#include <cuda_fp16.h>
#include <cstdint>

// out = concat(x, y, outer(x,y)) @ W^T, two kernels:
//  1) lin_pipe  : k < 1024 passthrough (proven, ~15us).
//  2) quad_fact : bilinear part FACTORIZED (out += sum_i x_i * (y @ W_i^T)),
//     Y fp16-staged once, Y fragments register-held, A regenerated via HMUL2.
//     THIS ROUND: each double-buffered W stage holds TWO i's (two 64x64 fp16
//     tiles); next-stage LDG issued at stage top has a full ~800cyc MMA phase
//     to land before its STS (kills the ~600cyc exposed W-latency found in
//     the R13 cycle audit) and barrier count halves. Per-element op order
//     unchanged -> rel_err must reproduce 4.137952e-4 bit-identically.

namespace {

constexpr int    kN1  = 512;
constexpr int    kOUT = 1024;
constexpr size_t kK   = 263168;

__device__ __forceinline__ uint32_t smem_u32(const void* p) {
  uint32_t a;
  asm("{ .reg .u64 t; cvta.to.shared.u64 t, %1; cvt.u32.u64 %0, t; }"
      : "=r"(a) : "l"(p));
  return a;
}
__device__ __forceinline__ void ldx4(uint32_t r[4], uint32_t addr) {
  asm volatile(
      "ldmatrix.sync.aligned.m8n8.x4.shared.b16 {%0,%1,%2,%3}, [%4];"
      : "=r"(r[0]), "=r"(r[1]), "=r"(r[2]), "=r"(r[3]) : "r"(addr));
}
__device__ __forceinline__ void mma16(float c[4], const uint32_t a[4],
                                      uint32_t b0, uint32_t b1) {
  asm volatile(
      "mma.sync.aligned.m16n8k16.row.col.f32.f16.f16.f32 "
      "{%0,%1,%2,%3}, {%4,%5,%6,%7}, {%8,%9}, {%0,%1,%2,%3};"
      : "+f"(c[0]), "+f"(c[1]), "+f"(c[2]), "+f"(c[3])
      : "r"(a[0]), "r"(a[1]), "r"(a[2]), "r"(a[3]), "r"(b0), "r"(b1));
}
__device__ __forceinline__ void sts128(uint32_t a, uint32_t v0, uint32_t v1,
                                       uint32_t v2, uint32_t v3) {
  asm volatile("st.shared.v4.b32 [%0], {%1,%2,%3,%4};"
               :: "r"(a), "r"(v0), "r"(v1), "r"(v2), "r"(v3) : "memory");
}
__device__ __forceinline__ void sts32(uint32_t a, float v) {
  asm volatile("st.shared.f32 [%0], %1;" :: "r"(a), "f"(v) : "memory");
}
__device__ __forceinline__ float lds32(uint32_t a) {
  float v;
  asm volatile("ld.shared.f32 %0, [%1];" : "=f"(v) : "r"(a));
  return v;
}
__device__ __forceinline__ uint32_t pack_h2(float v0, float v1) {
  __half2 h = __floats2half2_rn(v0, v1);
  return *reinterpret_cast<uint32_t*>(&h);
}
__device__ __forceinline__ void split_h2(float v0, float v1, uint32_t& h,
                                         uint32_t& l) {
  __half2 hh = __floats2half2_rn(v0, v1);
  h = *reinterpret_cast<uint32_t*>(&hh);
  l = pack_h2(v0 - __low2float(hh), v1 - __high2float(hh));
}
__device__ __forceinline__ uint32_t dup_h2(float f) {
  __half2 h = __half2half2(__float2half_rn(f));
  return *reinterpret_cast<uint32_t*>(&h);
}
__device__ __forceinline__ uint32_t hmul2u(uint32_t a, uint32_t b) {
  __half2 r = __hmul2(*reinterpret_cast<__half2*>(&a),
                      *reinterpret_cast<__half2*>(&b));
  return *reinterpret_cast<uint32_t*>(&r);
}

// ======================= linear part (k<1024): proven pipeline ==============
constexpr int L_LDA = 80, L_SZA = 128 * L_LDA, L_SZW = 128 * L_LDA;
constexpr int L_STAGE = L_SZA + 2 * L_SZW;
constexpr int LNH = 16;

__global__ void __launch_bounds__(256, 1)
lin_pipe(const float* __restrict__ x, const float* __restrict__ y,
         const float* __restrict__ W, float* __restrict__ out) {
  __shared__ __align__(16) uint8_t sm[2 * L_STAGE];
  const uint32_t sb = smem_u32(sm);

  const int tid = threadIdx.x, lane = tid & 31, warp = tid >> 5;
  const int wm = warp >> 2, wn = warp & 3;
  const int b0 = (blockIdx.x >> 1) * 128;
  const int half = blockIdx.x & 1;
  const int o0 = blockIdx.y * 128;
  const int gbase = half * LNH;

  const int prow = tid >> 1, phh = tid & 1;
  const float* __restrict__ xrow = x + (size_t)(b0 + prow) * kN1;
  const float* __restrict__ yrow = y + (size_t)(b0 + prow) * kN1;
  const float* __restrict__ wsrc = W + (size_t)(o0 + prow) * kK + phh * 16;
  const uint32_t pSt = prow * L_LDA + phh * 32;

  const uint32_t aoff =
      (uint32_t)((wm * 64 + (lane & 15)) * L_LDA + (lane >> 4) * 16);
  const uint32_t boff =
      (uint32_t)((wn * 32 + (lane & 7) + ((lane >> 4) & 1) * 8) * L_LDA +
                 ((lane >> 3) & 1) * 16);
  const int g = lane >> 2, t = lane & 3;

  float acc[4][4][4];
#pragma unroll
  for (int mt = 0; mt < 4; mt++)
#pragma unroll
    for (int nt = 0; nt < 4; nt++)
#pragma unroll
      for (int r = 0; r < 4; r++) acc[mt][nt][r] = 0.f;

  float4 av[4], wv[4];

  {  // chunk 0 into stage 0
    const int gc = gbase;
    const float* asrc = (gc < 16) ? (xrow + gc * 32 + phh * 16)
                                  : (yrow + (gc - 16) * 32 + phh * 16);
#pragma unroll
    for (int j = 0; j < 4; j++) av[j] = *(const float4*)(asrc + 4 * j);
    const float* wp = wsrc + (size_t)gc * 32;
#pragma unroll
    for (int j = 0; j < 4; j++) wv[j] = *(const float4*)(wp + 4 * j);

    uint32_t pA[8], pWh[8], pWl[8];
#pragma unroll
    for (int j = 0; j < 4; j++) {
      pA[2 * j]     = pack_h2(av[j].x, av[j].y);
      pA[2 * j + 1] = pack_h2(av[j].z, av[j].w);
      split_h2(wv[j].x, wv[j].y, pWh[2 * j], pWl[2 * j]);
      split_h2(wv[j].z, wv[j].w, pWh[2 * j + 1], pWl[2 * j + 1]);
    }
    sts128(sb + pSt, pA[0], pA[1], pA[2], pA[3]);
    sts128(sb + pSt + 16, pA[4], pA[5], pA[6], pA[7]);
    sts128(sb + L_SZA + pSt, pWh[0], pWh[1], pWh[2], pWh[3]);
    sts128(sb + L_SZA + pSt + 16, pWh[4], pWh[5], pWh[6], pWh[7]);
    sts128(sb + L_SZA + L_SZW + pSt, pWl[0], pWl[1], pWl[2], pWl[3]);
    sts128(sb + L_SZA + L_SZW + pSt + 16, pWl[4], pWl[5], pWl[6], pWl[7]);
  }
  __syncthreads();

  for (int ic = 0; ic < LNH; ic++) {
    const uint32_t rs = sb + (uint32_t)(ic & 1) * L_STAGE;
    const uint32_t ws = sb + (uint32_t)((ic + 1) & 1) * L_STAGE;
    const bool more = (ic + 1 < LNH);

    if (more) {
      const int gc = gbase + ic + 1;
      const float* asrc = (gc < 16) ? (xrow + gc * 32 + phh * 16)
                                    : (yrow + (gc - 16) * 32 + phh * 16);
#pragma unroll
      for (int j = 0; j < 4; j++) av[j] = *(const float4*)(asrc + 4 * j);
      const float* wp = wsrc + (size_t)gc * 32;
#pragma unroll
      for (int j = 0; j < 4; j++) wv[j] = *(const float4*)(wp + 4 * j);
    }

#pragma unroll
    for (int ks = 0; ks < 2; ks++) {
      const uint32_t ko = ks * 32;
      uint32_t aH[4][4], bH[2][4], bL[2][4];
#pragma unroll
      for (int mt = 0; mt < 4; mt++)
        ldx4(aH[mt], rs + aoff + mt * (16 * L_LDA) + ko);
#pragma unroll
      for (int p = 0; p < 2; p++) {
        ldx4(bH[p], rs + L_SZA + boff + p * (16 * L_LDA) + ko);
        ldx4(bL[p], rs + L_SZA + L_SZW + boff + p * (16 * L_LDA) + ko);
      }
#pragma unroll
      for (int mt = 0; mt < 4; mt++)
#pragma unroll
        for (int nt = 0; nt < 4; nt++) {
          const int p = nt >> 1, o = (nt & 1) * 2;
          mma16(acc[mt][nt], aH[mt], bH[p][o], bH[p][o + 1]);
          mma16(acc[mt][nt], aH[mt], bL[p][o], bL[p][o + 1]);
        }
    }

    if (more) {
      uint32_t pA[8], pWh[8], pWl[8];
#pragma unroll
      for (int j = 0; j < 4; j++) {
        pA[2 * j]     = pack_h2(av[j].x, av[j].y);
        pA[2 * j + 1] = pack_h2(av[j].z, av[j].w);
        split_h2(wv[j].x, wv[j].y, pWh[2 * j], pWl[2 * j]);
        split_h2(wv[j].z, wv[j].w, pWh[2 * j + 1], pWl[2 * j + 1]);
      }
      sts128(ws + pSt, pA[0], pA[1], pA[2], pA[3]);
      sts128(ws + pSt + 16, pA[4], pA[5], pA[6], pA[7]);
      sts128(ws + L_SZA + pSt, pWh[0], pWh[1], pWh[2], pWh[3]);
      sts128(ws + L_SZA + pSt + 16, pWh[4], pWh[5], pWh[6], pWh[7]);
      sts128(ws + L_SZA + L_SZW + pSt, pWl[0], pWl[1], pWl[2], pWl[3]);
      sts128(ws + L_SZA + L_SZW + pSt + 16, pWl[4], pWl[5], pWl[6], pWl[7]);
    }
    __syncthreads();
  }

#pragma unroll
  for (int mt = 0; mt < 4; mt++)
#pragma unroll
    for (int nt = 0; nt < 4; nt++) {
      const int r0 = b0 + wm * 64 + mt * 16 + g;
      const int c0 = o0 + wn * 32 + nt * 8 + 2 * t;
      atomicAdd(out + (size_t)r0 * kOUT + c0, acc[mt][nt][0]);
      atomicAdd(out + (size_t)r0 * kOUT + c0 + 1, acc[mt][nt][1]);
      atomicAdd(out + (size_t)(r0 + 8) * kOUT + c0, acc[mt][nt][2]);
      atomicAdd(out + (size_t)(r0 + 8) * kOUT + c0 + 1, acc[mt][nt][3]);
    }
}

// ======= bilinear part: factorized, 512 threads, 2 i's per W stage =========
constexpr int F_LDY  = 1040;
constexpr int F_YH   = 128 * F_LDY;              // 133120
constexpr int F_XS   = 64 * 512;                 // 32768
constexpr int F_LDW  = 144;
constexpr int F_WT   = 64 * F_LDW;               // 9216 (one 64x64 fp16 tile)
constexpr int F_STG  = 2 * F_WT;                 // stage = 2 tiles (2 i's)
constexpr int F_SMEM = F_YH + F_XS + 2 * F_STG;  // 202752
constexpr int NSTG   = 2048;                     // 4096 i-chunks / 2

__global__ void __launch_bounds__(512, 1)
quad_fact(const float* __restrict__ x, const float* __restrict__ y,
          const float* __restrict__ W, float* __restrict__ out) {
  extern __shared__ __align__(16) uint8_t dsm[];
  const uint32_t sY = smem_u32(dsm);
  const uint32_t sX = sY + F_YH;
  const uint32_t sW0 = sX + F_XS;

  const int tid = threadIdx.x, lane = tid & 31, warp = tid >> 5;
  const int wm = warp & 3, wn = warp >> 2;  // 4m x 4n, warp tile 32x16
  const int b0 = blockIdx.x * 128, o0 = blockIdx.y * 64;
  const int g = lane >> 2, t = lane & 3;

  // ---- stage Y as fp16 (once) ----
  {
    const int row = tid >> 2, h = tid & 3;
    const float* yr = y + (size_t)(b0 + row) * kN1 + h * 128;
    const uint32_t st = sY + row * F_LDY + h * 256;
#pragma unroll 4
    for (int c = 0; c < 128; c += 8) {
      float4 f0 = *(const float4*)(yr + c);
      float4 f1 = *(const float4*)(yr + c + 4);
      sts128(st + c * 2, pack_h2(f0.x, f0.y), pack_h2(f0.z, f0.w),
             pack_h2(f1.x, f1.y), pack_h2(f1.z, f1.w));
    }
  }

  // ---- W producer: 8 threads per o-row, 8 k-floats each ----
  const int prow = tid >> 3, pq = (tid & 7) * 8;
  const float* __restrict__ wbase = W + (size_t)(o0 + prow) * kK + pq + 1024;
  const uint32_t wSt = prow * F_LDW + pq * 2;

  // ---- x-slab staging: 4 threads per row, 16 i each ----
  const int xrw = tid >> 2, xih = tid & 3;
  const float* __restrict__ xbase = x + (size_t)(b0 + xrw) * kN1 + xih * 16;

  const uint32_t aoff =
      (uint32_t)((wm * 32 + (lane & 15)) * F_LDY + (lane >> 4) * 16);
  const uint32_t boff =
      (uint32_t)((wn * 16 + (lane & 7) + ((lane >> 4) & 1) * 8) * F_LDW +
                 ((lane >> 3) & 1) * 16);

  float acc[2][2][4], tot[2][2][4];
#pragma unroll
  for (int mt = 0; mt < 2; mt++)
#pragma unroll
    for (int nt = 0; nt < 2; nt++)
#pragma unroll
      for (int r = 0; r < 4; r++) { acc[mt][nt][r] = 0.f; tot[mt][nt][r] = 0.f; }

  // ---- prologue: x-slab iblk 0 + W stage 0 (i = 0 and 1, jb = 0) ----
  {
#pragma unroll
    for (int j = 0; j < 16; j += 4) {
      float4 v = *(const float4*)(xbase + j);
      const uint32_t a = sX + (xih * 16 + j) * 512 + xrw * 4;
      sts32(a, v.x); sts32(a + 512, v.y); sts32(a + 1024, v.z); sts32(a + 1536, v.w);
    }
    float4 a0 = *(const float4*)(wbase);
    float4 a1 = *(const float4*)(wbase + 4);
    float4 b0v = *(const float4*)(wbase + 512);
    float4 b1v = *(const float4*)(wbase + 516);
    sts128(sW0 + wSt, pack_h2(a0.x, a0.y), pack_h2(a0.z, a0.w),
           pack_h2(a1.x, a1.y), pack_h2(a1.z, a1.w));
    sts128(sW0 + F_WT + wSt, pack_h2(b0v.x, b0v.y), pack_h2(b0v.z, b0v.w),
           pack_h2(b1v.x, b1v.y), pack_h2(b1v.z, b1v.w));
  }
  __syncthreads();

  uint32_t yf[2][4][4];  // [mt][ks][reg], Y fragments for current jb
  float4 wv[4];          // next-stage W (two i's, 8 floats each)

  for (int s = 0; s < NSTG; s++) {
    const int c0i = 2 * s;           // first global i-chunk of this stage
    const int jb = c0i >> 9;

    if ((s & 255) == 0) {  // new j-block: reload Y fragments
#pragma unroll
      for (int mt = 0; mt < 2; mt++)
#pragma unroll
        for (int ks = 0; ks < 4; ks++)
          ldx4(yf[mt][ks], sY + aoff + jb * 128 + mt * (16 * F_LDY) + ks * 32);
    }
    if ((s & 31) == 0 && s) {  // new 64-i block: restage x-slab
      const int iblk = (c0i & 511) >> 6;
#pragma unroll
      for (int j = 0; j < 16; j += 4) {
        float4 v = *(const float4*)(xbase + iblk * 64 + j);
        const uint32_t a = sX + (xih * 16 + j) * 512 + xrw * 4;
        sts32(a, v.x); sts32(a + 512, v.y); sts32(a + 1024, v.z); sts32(a + 1536, v.w);
      }
      __syncthreads();
    }

    const uint32_t rs = sW0 + (uint32_t)(s & 1) * F_STG;
    const uint32_t ws = sW0 + (uint32_t)((s + 1) & 1) * F_STG;
    const bool more = (s + 1 < NSTG);

    // ---- LDG next stage's W first (MLP=4; full MMA phase to land) ----
    if (more) {
      const int c2 = 2 * (s + 1);
      const float* wp = wbase + (size_t)(c2 & 511) * 512 + (c2 >> 9) * 64;
      wv[0] = *(const float4*)(wp);
      wv[1] = *(const float4*)(wp + 4);
      wv[2] = *(const float4*)(wp + 512);
      wv[3] = *(const float4*)(wp + 516);
    }

    // ---- MMA phase: two i's, per-element op order identical to R13 ----
#pragma unroll
    for (int u = 0; u < 2; u++) {
      const int i = c0i + u;
      uint32_t xsd[2][2];
      const uint32_t xb = sX + (uint32_t)(i & 63) * 512 + (wm * 32) * 4;
#pragma unroll
      for (int mt = 0; mt < 2; mt++) {
        xsd[mt][0] = dup_h2(lds32(xb + (mt * 16 + g) * 4));
        xsd[mt][1] = dup_h2(lds32(xb + (mt * 16 + g + 8) * 4));
      }
      const uint32_t rsu = rs + (uint32_t)u * F_WT;
#pragma unroll
      for (int ks = 0; ks < 4; ks++) {
        uint32_t b[4];
        ldx4(b, rsu + boff + ks * 32);
#pragma unroll
        for (int mt = 0; mt < 2; mt++) {
          uint32_t as[4];
          as[0] = hmul2u(yf[mt][ks][0], xsd[mt][0]);
          as[1] = hmul2u(yf[mt][ks][1], xsd[mt][1]);
          as[2] = hmul2u(yf[mt][ks][2], xsd[mt][0]);
          as[3] = hmul2u(yf[mt][ks][3], xsd[mt][1]);
          mma16(acc[mt][0], as, b[0], b[1]);
          mma16(acc[mt][1], as, b[2], b[3]);
        }
      }
      if ((i & 15) == 15) {  // bounded RZ chain (64 adds) -> RN totals
#pragma unroll
        for (int mt = 0; mt < 2; mt++)
#pragma unroll
          for (int nt = 0; nt < 2; nt++)
#pragma unroll
            for (int r = 0; r < 4; r++) {
              tot[mt][nt][r] += acc[mt][nt][r];
              acc[mt][nt][r] = 0.f;
            }
      }
    }

    // ---- STS next stage (LDG above had the whole MMA phase to arrive) ----
    if (more) {
      sts128(ws + wSt, pack_h2(wv[0].x, wv[0].y), pack_h2(wv[0].z, wv[0].w),
             pack_h2(wv[1].x, wv[1].y), pack_h2(wv[1].z, wv[1].w));
      sts128(ws + F_WT + wSt, pack_h2(wv[2].x, wv[2].y), pack_h2(wv[2].z, wv[2].w),
             pack_h2(wv[3].x, wv[3].y), pack_h2(wv[3].z, wv[3].w));
    }
    __syncthreads();
  }

  // ---- epilogue: exclusive ownership, non-atomic += ----
#pragma unroll
  for (int mt = 0; mt < 2; mt++)
#pragma unroll
    for (int nt = 0; nt < 2; nt++) {
      const int r0 = b0 + wm * 32 + mt * 16 + g;
      const int c0 = o0 + wn * 16 + nt * 8 + 2 * t;
      out[(size_t)r0 * kOUT + c0]           += tot[mt][nt][0];
      out[(size_t)r0 * kOUT + c0 + 1]       += tot[mt][nt][1];
      out[(size_t)(r0 + 8) * kOUT + c0]     += tot[mt][nt][2];
      out[(size_t)(r0 + 8) * kOUT + c0 + 1] += tot[mt][nt][3];
    }
}

}  // namespace

extern "C" void kernel_launch(void* const* d_in, const int* in_sizes, int n_in,
                              void* d_out, int out_size) {
  (void)in_sizes; (void)n_in; (void)out_size;
  const float* x = (const float*)d_in[0];
  const float* y = (const float*)d_in[1];
  const float* W = (const float*)d_in[2];
  float* out = (float*)d_out;

  cudaFuncSetAttribute(quad_fact, cudaFuncAttributeMaxDynamicSharedMemorySize,
                       F_SMEM);

  cudaMemsetAsync(out, 0, (size_t)1024 * kOUT * sizeof(float));
  lin_pipe<<<dim3(16, 8), 256>>>(x, y, W, out);            // k < 1024
  quad_fact<<<dim3(8, 16), 512, F_SMEM>>>(x, y, W, out);   // bilinear part
}